// round 15
// baseline (speedup 1.0000x reference)
#include <cuda_runtime.h>
#include <cuda_fp16.h>
#include <math.h>
#include <stdint.h>

// Problem constants
#define CB   4
#define CL   512
#define CD   1024
#define CND  512
#define CED  64
#define CH   16
#define CMLP 2048
#define CDH  64
#define NTOK (CB*CL)        // 2048
#define MODW (6*CD)         // 6144
#define EPSF 1e-5f

// ---------------- scratch ----------------
__device__ __half g_sln_h[NTOK*CND];
__device__ __half g_t1_h[NTOK*CND];
__device__ float  g_mod[NTOK*MODW];
__device__ __half g_bias[(size_t)CB*CH*CL*CL];
__device__ __half g_x_h[NTOK*CD];
__device__ __half g_qkv_h[NTOK*3*CD];
__device__ __half g_o_h[NTOK*CD];
__device__ float  g_h2[NTOK*CD];
__device__ __half g_t2_h[NTOK*CMLP];
// fp16 weights: aw1 | aw2 | in_w | out_w | mw1 | mw2
#define OFF_AW1  0
#define OFF_AW2  (OFF_AW1 + 512*512)
#define OFF_INW  (OFF_AW2 + 6144*512)
#define OFF_OUTW (OFF_INW + 3072*1024)
#define OFF_MW1  (OFF_OUTW + 1024*1024)
#define OFF_MW2  (OFF_MW1 + 2048*1024)
#define WH_TOTAL (OFF_MW2 + 1024*2048)
__device__ __half g_wh[WH_TOTAL];

// ---------------- utils ----------------
__device__ __forceinline__ float warp_sum(float v) {
#pragma unroll
    for (int o = 16; o > 0; o >>= 1) v += __shfl_xor_sync(0xffffffffu, v, o);
    return v;
}
__device__ __forceinline__ void mma_tf32(float c[4], const uint32_t a[4], const uint32_t b[2]) {
    asm volatile(
        "mma.sync.aligned.m16n8k8.row.col.f32.tf32.tf32.f32 "
        "{%0,%1,%2,%3}, {%4,%5,%6,%7}, {%8,%9}, {%0,%1,%2,%3};"
        : "+f"(c[0]), "+f"(c[1]), "+f"(c[2]), "+f"(c[3])
        : "r"(a[0]), "r"(a[1]), "r"(a[2]), "r"(a[3]), "r"(b[0]), "r"(b[1]));
}
__device__ __forceinline__ void mma_fp16(float c[4], const uint32_t a[4], const uint32_t b[2]) {
    asm volatile(
        "mma.sync.aligned.m16n8k16.row.col.f32.f16.f16.f32 "
        "{%0,%1,%2,%3}, {%4,%5,%6,%7}, {%8,%9}, {%0,%1,%2,%3};"
        : "+f"(c[0]), "+f"(c[1]), "+f"(c[2]), "+f"(c[3])
        : "r"(a[0]), "r"(a[1]), "r"(a[2]), "r"(a[3]), "r"(b[0]), "r"(b[1]));
}
__device__ __forceinline__ uint32_t pack_h2(float lo, float hi) {
    __half2 h = __floats2half2_rn(lo, hi);
    return *(uint32_t*)&h;
}
__device__ __forceinline__ void ldsm_x4(uint32_t& d0, uint32_t& d1, uint32_t& d2, uint32_t& d3,
                                        uint32_t addr) {
    asm volatile("ldmatrix.sync.aligned.m8n8.x4.shared.b16 {%0,%1,%2,%3}, [%4];"
        : "=r"(d0), "=r"(d1), "=r"(d2), "=r"(d3) : "r"(addr));
}
#define CP_ASYNC16(dst_u32, src_ptr) \
    asm volatile("cp.async.cg.shared.global [%0], [%1], 16;" :: "r"(dst_u32), "l"(src_ptr))
#define CP_COMMIT() asm volatile("cp.async.commit_group;")
#define CP_WAIT(n)  asm volatile("cp.async.wait_group %0;" :: "n"(n))

// ---------------- all weights fp32 -> fp16, one kernel ----------------
__global__ void __launch_bounds__(256) cvt_all(
    const float4* __restrict__ s0, const float4* __restrict__ s1,
    const float4* __restrict__ s2, const float4* __restrict__ s3,
    const float4* __restrict__ s4, const float4* __restrict__ s5,
    uint2* __restrict__ dst)
{
    const int n0 = 512*512/4, n1 = 6144*512/4, n2 = 3072*1024/4,
              n3 = 1024*1024/4, n4 = 2048*1024/4, n5 = 1024*2048/4;
    int total = n0 + n1 + n2 + n3 + n4 + n5;
    for (int i = blockIdx.x * 256 + threadIdx.x; i < total; i += gridDim.x * 256) {
        int j = i; const float4* s;
        if (j < n0) s = s0;
        else { j -= n0; if (j < n1) s = s1;
        else { j -= n1; if (j < n2) s = s2;
        else { j -= n2; if (j < n3) s = s3;
        else { j -= n3; if (j < n4) s = s4;
        else { j -= n4; s = s5; }}}}}
        float4 v = s[j];
        uint2 u; u.x = pack_h2(v.x, v.y); u.y = pack_h2(v.z, v.w);
        dst[i] = u;
    }
}

// ---------------- LN(s)*w+b -> half, width 512 ----------------
__global__ void __launch_bounds__(128) ln_affine512h(
    const float* __restrict__ x, const float* __restrict__ w,
    const float* __restrict__ b, __half* __restrict__ out)
{
    int row = blockIdx.x;
    const float4* xr = (const float4*)(x + (size_t)row * CND);
    float4 v = xr[threadIdx.x];
    float s  = v.x + v.y + v.z + v.w;
    float ss = v.x*v.x + v.y*v.y + v.z*v.z + v.w*v.w;
    s = warp_sum(s); ss = warp_sum(ss);
    __shared__ float sh[8];
    int wid = threadIdx.x >> 5, lid = threadIdx.x & 31;
    if (lid == 0) { sh[wid] = s; sh[4 + wid] = ss; }
    __syncthreads();
    s  = sh[0] + sh[1] + sh[2] + sh[3];
    ss = sh[4] + sh[5] + sh[6] + sh[7];
    float mean = s * (1.0f / CND);
    float var  = ss * (1.0f / CND) - mean * mean;
    float rinv = rsqrtf(var + EPSF);
    int d = threadIdx.x * 4;
    float4 wv = *(const float4*)(w + d);
    float4 bv = *(const float4*)(b + d);
    uint2 u;
    u.x = pack_h2((v.x - mean) * rinv * wv.x + bv.x, (v.y - mean) * rinv * wv.y + bv.y);
    u.y = pack_h2((v.z - mean) * rinv * wv.z + bv.z, (v.w - mean) * rinv * wv.w + bv.w);
    ((uint2*)(out + (size_t)row * CND))[threadIdx.x] = u;
}

// ---------------- LN(h)*(1+scale)+shift -> half, width 1024 ----------------
__global__ void __launch_bounds__(256) ln_mod1024h(
    const float* __restrict__ x, const float* __restrict__ mod,
    int scale_off, int shift_off, __half* __restrict__ out)
{
    int row = blockIdx.x;
    float4 v = ((const float4*)(x + (size_t)row * CD))[threadIdx.x];
    float s  = v.x + v.y + v.z + v.w;
    float ss = v.x*v.x + v.y*v.y + v.z*v.z + v.w*v.w;
    s = warp_sum(s); ss = warp_sum(ss);
    __shared__ float sh[16];
    int wid = threadIdx.x >> 5, lid = threadIdx.x & 31;
    if (lid == 0) { sh[wid] = s; sh[8 + wid] = ss; }
    __syncthreads();
    s = 0.f; ss = 0.f;
#pragma unroll
    for (int i = 0; i < 8; i++) { s += sh[i]; ss += sh[8 + i]; }
    float mean = s * (1.0f / CD);
    float var  = ss * (1.0f / CD) - mean * mean;
    float rinv = rsqrtf(var + EPSF);
    int d = threadIdx.x * 4;
    const float* mrow = mod + (size_t)row * MODW;
    float4 sc = *(const float4*)(mrow + scale_off + d);
    float4 sf = *(const float4*)(mrow + shift_off + d);
    uint2 u;
    u.x = pack_h2(((v.x - mean) * rinv) * (1.0f + sc.x) + sf.x,
                  ((v.y - mean) * rinv) * (1.0f + sc.y) + sf.y);
    u.y = pack_h2(((v.z - mean) * rinv) * (1.0f + sc.z) + sf.z,
                  ((v.w - mean) * rinv) * (1.0f + sc.w) + sf.w);
    ((uint2*)(out + (size_t)row * CD))[threadIdx.x] = u;
}

// ---------------- fp16 NT GEMM: 64x128 tile, 3-stage cp.async, ldmatrix ----------------
// Block M=64, N=128, K=32/stage. 8 warps as 2(M) x 4(N); warp tile 32x32.
// EPI 0: float C = acc + bias
// EPI 1: half  C = silu(acc + bias)
// EPI 2: float C = res + (acc + bias) * gate
// EPI 3: half  C = acc + bias
#define ST_A (64 * 20)
#define ST_W (128 * 20)
#define GEMM_SMEM_H (3 * (ST_A + ST_W) * 4)   // 46 KB
template<int EPI>
__global__ void __launch_bounds__(256, 3) gemm_h(
    const __half* __restrict__ A, const __half* __restrict__ W,
    const float* __restrict__ bias, void* __restrict__ Cv,
    int M, int N, int K,
    const float* __restrict__ res, const float* __restrict__ gate, int gate_off)
{
    extern __shared__ uint32_t dynh[];
    uint32_t* As = dynh;                   // [3][64][20]
    uint32_t* Ws = dynh + 3 * ST_A;        // [3][128][20]

    int bm = blockIdx.y * 64;
    int bn = blockIdx.x * 128;
    int tid  = threadIdx.x;
    int warp = tid >> 5, lane = tid & 31;
    int g = lane >> 2, t = lane & 3;
    int wm = (warp & 1) * 32;              // 2 warps in M
    int wn = (warp >> 1) * 32;             // 4 warps in N

    int lmA_row = lane & 15;
    int lmA_koff = (lane >> 4) * 4;
    int lmB_row = ((lane >> 4) * 8) + (lane & 7);
    int lmB_koff = ((lane >> 3) & 1) * 4;

    float acc[2][4][4];
#pragma unroll
    for (int i = 0; i < 2; i++)
#pragma unroll
        for (int j = 0; j < 4; j++)
#pragma unroll
            for (int q = 0; q < 4; q++) acc[i][j][q] = 0.f;

    // load slots: A = 1 chunk/thread (64 rows x 4 segs), W = 2 chunks/thread
    int arow = tid >> 2,            aseg = tid & 3;
    int wrow0 = tid >> 2,           wseg = tid & 3;
    int wrow1 = (tid + 256) >> 2;

    int nIter = K >> 5;

    // prologue: stages 0,1
#pragma unroll
    for (int s = 0; s < 2; s++) {
        uint32_t* Ab = As + s * ST_A;
        uint32_t* Wb = Ws + s * ST_W;
        int k0 = s << 5;
        uint32_t da = (uint32_t)__cvta_generic_to_shared(&Ab[arow * 20 + aseg * 4]);
        CP_ASYNC16(da, A + (size_t)(bm + arow) * K + k0 + aseg * 8);
        uint32_t dw0 = (uint32_t)__cvta_generic_to_shared(&Wb[wrow0 * 20 + wseg * 4]);
        CP_ASYNC16(dw0, W + (size_t)(bn + wrow0) * K + k0 + wseg * 8);
        uint32_t dw1 = (uint32_t)__cvta_generic_to_shared(&Wb[wrow1 * 20 + wseg * 4]);
        CP_ASYNC16(dw1, W + (size_t)(bn + wrow1) * K + k0 + wseg * 8);
        CP_COMMIT();
    }

    int buf = 0;
    for (int it = 0; it < nIter; ++it) {
        if (it + 1 < nIter) { CP_WAIT(1); } else { CP_WAIT(0); }
        __syncthreads();

        if (it + 2 < nIter) {
            int bnext = buf + 2; if (bnext >= 3) bnext -= 3;
            uint32_t* Ab = As + bnext * ST_A;
            uint32_t* Wb = Ws + bnext * ST_W;
            int k0 = (it + 2) << 5;
            uint32_t da = (uint32_t)__cvta_generic_to_shared(&Ab[arow * 20 + aseg * 4]);
            CP_ASYNC16(da, A + (size_t)(bm + arow) * K + k0 + aseg * 8);
            uint32_t dw0 = (uint32_t)__cvta_generic_to_shared(&Wb[wrow0 * 20 + wseg * 4]);
            CP_ASYNC16(dw0, W + (size_t)(bn + wrow0) * K + k0 + wseg * 8);
            uint32_t dw1 = (uint32_t)__cvta_generic_to_shared(&Wb[wrow1 * 20 + wseg * 4]);
            CP_ASYNC16(dw1, W + (size_t)(bn + wrow1) * K + k0 + wseg * 8);
            CP_COMMIT();
        }

        const uint32_t* Ab = As + buf * ST_A;
        const uint32_t* Wb = Ws + buf * ST_W;
#pragma unroll
        for (int ks = 0; ks < 2; ks++) {
            int kp = ks * 8;
            uint32_t af[2][4];
#pragma unroll
            for (int mt = 0; mt < 2; mt++) {
                int r0 = wm + mt * 16;
                uint32_t addr = (uint32_t)__cvta_generic_to_shared(
                    &Ab[(size_t)(r0 + lmA_row) * 20 + kp + lmA_koff]);
                ldsm_x4(af[mt][0], af[mt][1], af[mt][2], af[mt][3], addr);
            }
            uint32_t bf[4][2];
#pragma unroll
            for (int np = 0; np < 2; np++) {
                int c0 = wn + np * 16;
                uint32_t addr = (uint32_t)__cvta_generic_to_shared(
                    &Wb[(size_t)(c0 + lmB_row) * 20 + kp + lmB_koff]);
                ldsm_x4(bf[2*np][0], bf[2*np][1], bf[2*np+1][0], bf[2*np+1][1], addr);
            }
#pragma unroll
            for (int mt = 0; mt < 2; mt++)
#pragma unroll
                for (int nt = 0; nt < 4; nt++)
                    mma_fp16(acc[mt][nt], af[mt], bf[nt]);
        }
        buf++; if (buf >= 3) buf = 0;
    }

#pragma unroll
    for (int mt = 0; mt < 2; mt++) {
#pragma unroll
        for (int half = 0; half < 2; half++) {
            int row = bm + wm + mt * 16 + g + half * 8;
            const float* rr = (EPI == 2) ? res + (size_t)row * N : nullptr;
            const float* gr = (EPI == 2) ? gate + (size_t)row * MODW + gate_off : nullptr;
#pragma unroll
            for (int nt = 0; nt < 4; nt++) {
                int col = bn + wn + nt * 8 + 2 * t;
                float v0 = acc[mt][nt][half * 2 + 0] + bias[col];
                float v1 = acc[mt][nt][half * 2 + 1] + bias[col + 1];
                if (EPI == 1) {
                    v0 = v0 / (1.0f + expf(-v0));
                    v1 = v1 / (1.0f + expf(-v1));
                }
                if (EPI == 1 || EPI == 3) {
                    __half* cr = (__half*)Cv + (size_t)row * N;
                    *(uint32_t*)(cr + col) = pack_h2(v0, v1);
                } else {
                    if (EPI == 2) {
                        v0 = rr[col]     + v0 * gr[col];
                        v1 = rr[col + 1] + v1 * gr[col + 1];
                    }
                    float* cr = (float*)Cv + (size_t)row * N;
                    float2 o2; o2.x = v0; o2.y = v1;
                    *(float2*)(cr + col) = o2;
                }
            }
        }
    }
}

// ---------------- edge bias (frozen since round 9) ----------------
__global__ void __launch_bounds__(128) edge_bias_mma(
    const float* __restrict__ p, const float* __restrict__ lnw, const float* __restrict__ lnb,
    const float* __restrict__ ew, const float* __restrict__ eb, __half* __restrict__ bias)
{
    __shared__ float rows[128][68];
    __shared__ float W2T[16][68];
    __shared__ float meanv[128], rinvv[128], c1s[16], c2s[16];
    int tid = threadIdx.x;
    size_t base = (size_t)blockIdx.x * 128;

#pragma unroll
    for (int r = 0; r < 16; r++) {
        int id  = tid + r * 128;
        int row = id >> 4;
        int c4  = (id & 15) * 4;
        *(float4*)&rows[row][c4] = *(const float4*)(p + (base + row) * 64 + c4);
    }
    for (int i = tid; i < 1024; i += 128) {
        int h = i >> 6, k = i & 63;
        W2T[h][k] = ew[i] * lnw[k];
    }
    if (tid < 16) {
        float a = 0.f, b2 = 0.f;
        for (int k = 0; k < 64; k++) {
            float e = ew[tid * 64 + k];
            a  += lnw[k] * e;
            b2 += lnb[k] * e;
        }
        c1s[tid] = a;
        c2s[tid] = b2 + eb[tid];
    }
    __syncthreads();

    {
        float s = 0.f, ss = 0.f;
#pragma unroll
        for (int q = 0; q < 16; q++) {
            float4 x = *(const float4*)&rows[tid][q * 4];
            s  += x.x + x.y + x.z + x.w;
            ss += x.x*x.x + x.y*x.y + x.z*x.z + x.w*x.w;
        }
        float mean = s * (1.0f / 64.0f);
        float var  = ss * (1.0f / 64.0f) - mean * mean;
        meanv[tid] = mean;
        rinvv[tid] = rsqrtf(var + EPSF);
    }
    __syncthreads();

    int warp = tid >> 5, lane = tid & 31;
    int g = lane >> 2, t = lane & 3;
    float acc[2][2][4];
#pragma unroll
    for (int i = 0; i < 2; i++)
#pragma unroll
        for (int j = 0; j < 2; j++)
#pragma unroll
            for (int q = 0; q < 4; q++) acc[i][j][q] = 0.f;

#pragma unroll
    for (int ks = 0; ks < 8; ks++) {
        int kk = ks * 8;
        uint32_t af[2][4];
#pragma unroll
        for (int mt = 0; mt < 2; mt++) {
            int r0 = warp * 32 + mt * 16 + g;
            af[mt][0] = __float_as_uint(rows[r0][kk + t]);
            af[mt][1] = __float_as_uint(rows[r0 + 8][kk + t]);
            af[mt][2] = __float_as_uint(rows[r0][kk + t + 4]);
            af[mt][3] = __float_as_uint(rows[r0 + 8][kk + t + 4]);
        }
        uint32_t bf[2][2];
#pragma unroll
        for (int nt = 0; nt < 2; nt++) {
            int c0 = nt * 8 + g;
            bf[nt][0] = __float_as_uint(W2T[c0][kk + t]);
            bf[nt][1] = __float_as_uint(W2T[c0][kk + t + 4]);
        }
#pragma unroll
        for (int mt = 0; mt < 2; mt++)
#pragma unroll
            for (int nt = 0; nt < 2; nt++)
                mma_tf32(acc[mt][nt], af[mt], bf[nt]);
    }

    int b  = (int)(base >> 18);
    int ij = (int)(base & 262143);
    int i  = ij >> 9;
    int j0 = ij & 511;
    __half* bb = bias + (((size_t)b * 16) * 512 + i) * 512 + j0;
#pragma unroll
    for (int mt = 0; mt < 2; mt++) {
#pragma unroll
        for (int half = 0; half < 2; half++) {
            int rl = warp * 32 + mt * 16 + g + half * 8;
            float m  = meanv[rl];
            float rv = rinvv[rl];
#pragma unroll
            for (int nt = 0; nt < 2; nt++) {
#pragma unroll
                for (int c = 0; c < 2; c++) {
                    int h = nt * 8 + 2 * t + c;
                    bb[(size_t)h * 512 * 512 + rl] =
                        __float2half(rv * (acc[mt][nt][half * 2 + c] - m * c1s[h]) + c2s[h]);
                }
            }
        }
    }
}

// ---------------- flash v2: all-fp16 MMA, register-resident P ----------------
__global__ void __launch_bounds__(256) flash_h(
    const __half* __restrict__ bias, const __half* __restrict__ qkvh, __half* __restrict__ o)
{
    __shared__ uint32_t Qh[128 * 36];
    __shared__ uint32_t Kh[64 * 36];
    __shared__ uint32_t Vt[64 * 36];

    int bh = blockIdx.y; int b = bh >> 4, h = bh & 15;
    int i0 = blockIdx.x * 128;
    int tid  = threadIdx.x;
    int warp = tid >> 5, lane = tid & 31;
    int g = lane >> 2, t = lane & 3;
    int r0 = warp * 16 + g;

    const __half* qb = qkvh + (size_t)(b * CL) * (3 * CD) + h * CDH;
    const __half* kb = qb + CD;
    const __half* vb = qb + 2 * CD;
    const __half* bbase = bias + ((size_t)bh * CL + i0) * CL;

#pragma unroll
    for (int r = 0; r < 4; r++) {
        int id  = tid + r * 256;
        int row = id >> 3, seg = id & 7;
        uint32_t dst = (uint32_t)__cvta_generic_to_shared(&Qh[row * 36 + seg * 4]);
        CP_ASYNC16(dst, qb + (size_t)(i0 + row) * (3 * CD) + seg * 8);
    }
    CP_COMMIT();

    float Oa[8][4];
#pragma unroll
    for (int nt = 0; nt < 8; nt++)
#pragma unroll
        for (int q = 0; q < 4; q++) Oa[nt][q] = 0.f;
    float m0 = -1e30f, m1 = -1e30f, l0 = 0.f, l1 = 0.f;

    for (int j0 = 0; j0 < CL; j0 += 64) {
#pragma unroll
        for (int r = 0; r < 2; r++) {
            int id  = tid + r * 256;
            int row = id >> 3, seg = id & 7;
            uint32_t dst = (uint32_t)__cvta_generic_to_shared(&Kh[row * 36 + seg * 4]);
            CP_ASYNC16(dst, kb + (size_t)(j0 + row) * (3 * CD) + seg * 8);
        }
        CP_COMMIT();
#pragma unroll
        for (int r = 0; r < 2; r++) {
            int jw = (tid >> 4) + r * 16;
            int dg = tid & 15;
            const __half* va = vb + (size_t)(j0 + 2 * jw) * (3 * CD) + dg * 4;
            uint2 ua = *(const uint2*)va;
            uint2 ub = *(const uint2*)(va + 3 * CD);
            Vt[(dg * 4 + 0) * 36 + jw] = (ua.x & 0xFFFFu)  | (ub.x << 16);
            Vt[(dg * 4 + 1) * 36 + jw] = (ua.x >> 16)      | (ub.x & 0xFFFF0000u);
            Vt[(dg * 4 + 2) * 36 + jw] = (ua.y & 0xFFFFu)  | (ub.y << 16);
            Vt[(dg * 4 + 3) * 36 + jw] = (ua.y >> 16)      | (ub.y & 0xFFFF0000u);
        }
        CP_WAIT(0);
        __syncthreads();

        float sa[8][4];
#pragma unroll
        for (int nt = 0; nt < 8; nt++)
#pragma unroll
            for (int q = 0; q < 4; q++) sa[nt][q] = 0.f;
#pragma unroll
        for (int ks = 0; ks < 4; ks++) {
            int kp = ks * 8;
            uint32_t af[4];
            af[0] = Qh[r0 * 36 + kp + t];
            af[1] = Qh[(r0 + 8) * 36 + kp + t];
            af[2] = Qh[r0 * 36 + kp + t + 4];
            af[3] = Qh[(r0 + 8) * 36 + kp + t + 4];
#pragma unroll
            for (int nt = 0; nt < 8; nt++) {
                int c0 = nt * 8 + g;
                uint32_t bf[2];
                bf[0] = Kh[c0 * 36 + kp + t];
                bf[1] = Kh[c0 * 36 + kp + t + 4];
                mma_fp16(sa[nt], af, bf);
            }
        }

        float mt0 = -1e30f, mt1 = -1e30f;
#pragma unroll
        for (int nt = 0; nt < 8; nt++) {
            int col = j0 + nt * 8 + 2 * t;
            float2 b0 = __half22float2(*(const __half2*)(bbase + (size_t)r0 * CL + col));
            float2 b1 = __half22float2(*(const __half2*)(bbase + (size_t)(r0 + 8) * CL + col));
            sa[nt][0] = fmaf(sa[nt][0], 0.125f, b0.x);
            sa[nt][1] = fmaf(sa[nt][1], 0.125f, b0.y);
            sa[nt][2] = fmaf(sa[nt][2], 0.125f, b1.x);
            sa[nt][3] = fmaf(sa[nt][3], 0.125f, b1.y);
            mt0 = fmaxf(mt0, fmaxf(sa[nt][0], sa[nt][1]));
            mt1 = fmaxf(mt1, fmaxf(sa[nt][2], sa[nt][3]));
        }
#pragma unroll
        for (int x = 1; x <= 2; x <<= 1) {
            mt0 = fmaxf(mt0, __shfl_xor_sync(0xffffffffu, mt0, x));
            mt1 = fmaxf(mt1, __shfl_xor_sync(0xffffffffu, mt1, x));
        }
        float mn0 = fmaxf(m0, mt0), mn1 = fmaxf(m1, mt1);
        float sc0 = expf(m0 - mn0), sc1 = expf(m1 - mn1);
        m0 = mn0; m1 = mn1;

        float ps0 = 0.f, ps1 = 0.f;
#pragma unroll
        for (int nt = 0; nt < 8; nt++) {
            sa[nt][0] = expf(sa[nt][0] - m0);
            sa[nt][1] = expf(sa[nt][1] - m0);
            sa[nt][2] = expf(sa[nt][2] - m1);
            sa[nt][3] = expf(sa[nt][3] - m1);
            ps0 += sa[nt][0] + sa[nt][1];
            ps1 += sa[nt][2] + sa[nt][3];
        }
#pragma unroll
        for (int x = 1; x <= 2; x <<= 1) {
            ps0 += __shfl_xor_sync(0xffffffffu, ps0, x);
            ps1 += __shfl_xor_sync(0xffffffffu, ps1, x);
        }
        l0 = l0 * sc0 + ps0;
        l1 = l1 * sc1 + ps1;
#pragma unroll
        for (int nt = 0; nt < 8; nt++) {
            Oa[nt][0] *= sc0; Oa[nt][1] *= sc0;
            Oa[nt][2] *= sc1; Oa[nt][3] *= sc1;
        }

#pragma unroll
        for (int ks = 0; ks < 4; ks++) {
            uint32_t af[4];
            af[0] = pack_h2(sa[2*ks][0],     sa[2*ks][1]);
            af[1] = pack_h2(sa[2*ks][2],     sa[2*ks][3]);
            af[2] = pack_h2(sa[2*ks + 1][0], sa[2*ks + 1][1]);
            af[3] = pack_h2(sa[2*ks + 1][2], sa[2*ks + 1][3]);
#pragma unroll
            for (int nt = 0; nt < 8; nt++) {
                int c0 = nt * 8 + g;
                uint32_t bf[2];
                bf[0] = Vt[c0 * 36 + ks * 8 + t];
                bf[1] = Vt[c0 * 36 + ks * 8 + t + 4];
                mma_fp16(Oa[nt], af, bf);
            }
        }
        __syncthreads();
    }

    float il0 = 1.0f / l0, il1 = 1.0f / l1;
    __half* o0 = o + (size_t)(b * CL + i0 + r0) * CD + h * CDH;
    __half* o1 = o + (size_t)(b * CL + i0 + r0 + 8) * CD + h * CDH;
#pragma unroll
    for (int nt = 0; nt < 8; nt++) {
        int d = nt * 8 + 2 * t;
        *(uint32_t*)(o0 + d) = pack_h2(Oa[nt][0] * il0, Oa[nt][1] * il0);
        *(uint32_t*)(o1 + d) = pack_h2(Oa[nt][2] * il1, Oa[nt][3] * il1);
    }
}

// ---------------- launch ----------------
extern "C" void kernel_launch(void* const* d_in, const int* in_sizes, int n_in,
                              void* d_out, int out_size)
{
    const float* h_in  = (const float*)d_in[0];
    const float* s_in  = (const float*)d_in[1];
    const float* p_in  = (const float*)d_in[2];
    const float* aln_w = (const float*)d_in[3];
    const float* aln_b = (const float*)d_in[4];
    const float* aw1   = (const float*)d_in[5];
    const float* ab1   = (const float*)d_in[6];
    const float* aw2   = (const float*)d_in[7];
    const float* ab2   = (const float*)d_in[8];
    const float* eln_w = (const float*)d_in[9];
    const float* eln_b = (const float*)d_in[10];
    const float* ew    = (const float*)d_in[11];
    const float* eb    = (const float*)d_in[12];
    const float* in_w  = (const float*)d_in[13];
    const float* in_b  = (const float*)d_in[14];
    const float* out_w = (const float*)d_in[15];
    const float* out_b = (const float*)d_in[16];
    const float* mw1   = (const float*)d_in[17];
    const float* mb1   = (const float*)d_in[18];
    const float* mw2   = (const float*)d_in[19];
    const float* mb2   = (const float*)d_in[20];
    float* out = (float*)d_out;

    float *mod, *h2;
    __half *sln_h, *t1_h, *x_h, *qkv_h, *o_h, *t2_h, *biasb, *wh;
    cudaGetSymbolAddress((void**)&sln_h, g_sln_h);
    cudaGetSymbolAddress((void**)&t1_h,  g_t1_h);
    cudaGetSymbolAddress((void**)&mod,   g_mod);
    cudaGetSymbolAddress((void**)&biasb, g_bias);
    cudaGetSymbolAddress((void**)&x_h,   g_x_h);
    cudaGetSymbolAddress((void**)&qkv_h, g_qkv_h);
    cudaGetSymbolAddress((void**)&o_h,   g_o_h);
    cudaGetSymbolAddress((void**)&h2,    g_h2);
    cudaGetSymbolAddress((void**)&t2_h,  g_t2_h);
    cudaGetSymbolAddress((void**)&wh,    g_wh);

    cudaFuncSetAttribute(gemm_h<0>, cudaFuncAttributeMaxDynamicSharedMemorySize, GEMM_SMEM_H);
    cudaFuncSetAttribute(gemm_h<1>, cudaFuncAttributeMaxDynamicSharedMemorySize, GEMM_SMEM_H);
    cudaFuncSetAttribute(gemm_h<2>, cudaFuncAttributeMaxDynamicSharedMemorySize, GEMM_SMEM_H);
    cudaFuncSetAttribute(gemm_h<3>, cudaFuncAttributeMaxDynamicSharedMemorySize, GEMM_SMEM_H);

    // ---- fork edge_bias onto the per-thread stream (parallel graph branch) ----
    cudaEvent_t ev_fork, ev_join;
    cudaEventCreateWithFlags(&ev_fork, cudaEventDisableTiming);
    cudaEventCreateWithFlags(&ev_join, cudaEventDisableTiming);
    cudaEventRecord(ev_fork, 0);
    cudaStreamWaitEvent(cudaStreamPerThread, ev_fork, 0);
    edge_bias_mma<<<(CB * CL * CL) / 128, 128, 0, cudaStreamPerThread>>>(
        p_in, eln_w, eln_b, ew, eb, biasb);
    cudaEventRecord(ev_join, cudaStreamPerThread);

    // ---- main chain (legacy stream) ----
    cvt_all<<<1024, 256>>>((const float4*)aw1, (const float4*)aw2, (const float4*)in_w,
                           (const float4*)out_w, (const float4*)mw1, (const float4*)mw2,
                           (uint2*)wh);

    // adaLN modulation chain
    ln_affine512h<<<NTOK, 128>>>(s_in, aln_w, aln_b, sln_h);
    gemm_h<1><<<dim3(CND / 128, NTOK / 64), 256, GEMM_SMEM_H>>>(sln_h, wh + OFF_AW1, ab1,
        t1_h, NTOK, CND, CND, nullptr, nullptr, 0);
    gemm_h<0><<<dim3(MODW / 128, NTOK / 64), 256, GEMM_SMEM_H>>>(t1_h, wh + OFF_AW2, ab2,
        mod, NTOK, MODW, CND, nullptr, nullptr, 0);

    // attention branch
    ln_mod1024h<<<NTOK, 256>>>(h_in, mod, /*scale*/CD, /*shift*/0, x_h);
    gemm_h<3><<<dim3(3 * CD / 128, NTOK / 64), 256, GEMM_SMEM_H>>>(x_h, wh + OFF_INW, in_b,
        qkv_h, NTOK, 3 * CD, CD, nullptr, nullptr, 0);

    // join: flash needs the edge bias
    cudaStreamWaitEvent(0, ev_join, 0);
    flash_h<<<dim3(CL / 128, CB * CH), 256>>>(biasb, qkv_h, o_h);
    gemm_h<2><<<dim3(CD / 128, NTOK / 64), 256, GEMM_SMEM_H>>>(o_h, wh + OFF_OUTW, out_b,
        h2, NTOK, CD, CD, h_in, mod, 2 * CD);

    // gated MLP branch
    ln_mod1024h<<<NTOK, 256>>>(h2, mod, /*scale*/4 * CD, /*shift*/3 * CD, x_h);
    gemm_h<1><<<dim3(CMLP / 128, NTOK / 64), 256, GEMM_SMEM_H>>>(x_h, wh + OFF_MW1, mb1,
        t2_h, NTOK, CMLP, CD, nullptr, nullptr, 0);
    gemm_h<2><<<dim3(CD / 128, NTOK / 64), 256, GEMM_SMEM_H>>>(t2_h, wh + OFF_MW2, mb2,
        out, NTOK, CD, CMLP, h2, mod, 5 * CD);
    // events intentionally not destroyed (capture-legal; no device memory)
}

// round 16
// speedup vs baseline: 1.0344x; 1.0344x over previous
#include <cuda_runtime.h>
#include <cuda_fp16.h>
#include <math.h>
#include <stdint.h>

// Problem constants
#define CB   4
#define CL   512
#define CD   1024
#define CND  512
#define CED  64
#define CH   16
#define CMLP 2048
#define CDH  64
#define NTOK (CB*CL)        // 2048
#define MODW (6*CD)         // 6144
#define EPSF 1e-5f

// ---------------- scratch ----------------
__device__ __half g_sln_h[NTOK*CND];
__device__ __half g_t1_h[NTOK*CND];
__device__ float  g_mod[NTOK*MODW];
__device__ __half g_bias[(size_t)CB*CH*CL*CL];
__device__ __half g_x_h[NTOK*CD];
__device__ __half g_qkv_h[NTOK*3*CD];
__device__ __half g_o_h[NTOK*CD];
__device__ float  g_h2[NTOK*CD];
__device__ __half g_t2_h[NTOK*CMLP];
// fp16 weights
#define OFF_AW1  0
#define OFF_AW2  (OFF_AW1 + 512*512)
#define OFF_INW  (OFF_AW2 + 6144*512)
#define OFF_OUTW (OFF_INW + 3072*1024)
#define OFF_MW1  (OFF_OUTW + 1024*1024)
#define OFF_MW2  (OFF_MW1 + 2048*1024)
#define WH_TOTAL (OFF_MW2 + 1024*2048)
__device__ __half g_wh[WH_TOTAL];

// ---------------- utils ----------------
__device__ __forceinline__ float warp_sum(float v) {
#pragma unroll
    for (int o = 16; o > 0; o >>= 1) v += __shfl_xor_sync(0xffffffffu, v, o);
    return v;
}
__device__ __forceinline__ void mma_tf32(float c[4], const uint32_t a[4], const uint32_t b[2]) {
    asm volatile(
        "mma.sync.aligned.m16n8k8.row.col.f32.tf32.tf32.f32 "
        "{%0,%1,%2,%3}, {%4,%5,%6,%7}, {%8,%9}, {%0,%1,%2,%3};"
        : "+f"(c[0]), "+f"(c[1]), "+f"(c[2]), "+f"(c[3])
        : "r"(a[0]), "r"(a[1]), "r"(a[2]), "r"(a[3]), "r"(b[0]), "r"(b[1]));
}
__device__ __forceinline__ void mma_fp16(float c[4], const uint32_t a[4], const uint32_t b[2]) {
    asm volatile(
        "mma.sync.aligned.m16n8k16.row.col.f32.f16.f16.f32 "
        "{%0,%1,%2,%3}, {%4,%5,%6,%7}, {%8,%9}, {%0,%1,%2,%3};"
        : "+f"(c[0]), "+f"(c[1]), "+f"(c[2]), "+f"(c[3])
        : "r"(a[0]), "r"(a[1]), "r"(a[2]), "r"(a[3]), "r"(b[0]), "r"(b[1]));
}
__device__ __forceinline__ uint32_t pack_h2(float lo, float hi) {
    __half2 h = __floats2half2_rn(lo, hi);
    return *(uint32_t*)&h;
}
__device__ __forceinline__ void ldsm_x4(uint32_t& d0, uint32_t& d1, uint32_t& d2, uint32_t& d3,
                                        uint32_t addr) {
    asm volatile("ldmatrix.sync.aligned.m8n8.x4.shared.b16 {%0,%1,%2,%3}, [%4];"
        : "=r"(d0), "=r"(d1), "=r"(d2), "=r"(d3) : "r"(addr));
}
#define CP_ASYNC16(dst_u32, src_ptr) \
    asm volatile("cp.async.cg.shared.global [%0], [%1], 16;" :: "r"(dst_u32), "l"(src_ptr))
#define CP_COMMIT() asm volatile("cp.async.commit_group;")
#define CP_WAIT(n)  asm volatile("cp.async.wait_group %0;" :: "n"(n))

// ---------------- all weights fp32 -> fp16, one kernel ----------------
__global__ void __launch_bounds__(256) cvt_all(
    const float4* __restrict__ s0, const float4* __restrict__ s1,
    const float4* __restrict__ s2, const float4* __restrict__ s3,
    const float4* __restrict__ s4, const float4* __restrict__ s5,
    uint2* __restrict__ dst)
{
    const int n0 = 512*512/4, n1 = 6144*512/4, n2 = 3072*1024/4,
              n3 = 1024*1024/4, n4 = 2048*1024/4, n5 = 1024*2048/4;
    int total = n0 + n1 + n2 + n3 + n4 + n5;
    for (int i = blockIdx.x * 256 + threadIdx.x; i < total; i += gridDim.x * 256) {
        int j = i; const float4* s;
        if (j < n0) s = s0;
        else { j -= n0; if (j < n1) s = s1;
        else { j -= n1; if (j < n2) s = s2;
        else { j -= n2; if (j < n3) s = s3;
        else { j -= n3; if (j < n4) s = s4;
        else { j -= n4; s = s5; }}}}}
        float4 v = s[j];
        uint2 u; u.x = pack_h2(v.x, v.y); u.y = pack_h2(v.z, v.w);
        dst[i] = u;
    }
}

// ---------------- LN(s)*w+b -> half, width 512 ----------------
__global__ void __launch_bounds__(128) ln_affine512h(
    const float* __restrict__ x, const float* __restrict__ w,
    const float* __restrict__ b, __half* __restrict__ out)
{
    int row = blockIdx.x;
    const float4* xr = (const float4*)(x + (size_t)row * CND);
    float4 v = xr[threadIdx.x];
    float s  = v.x + v.y + v.z + v.w;
    float ss = v.x*v.x + v.y*v.y + v.z*v.z + v.w*v.w;
    s = warp_sum(s); ss = warp_sum(ss);
    __shared__ float sh[8];
    int wid = threadIdx.x >> 5, lid = threadIdx.x & 31;
    if (lid == 0) { sh[wid] = s; sh[4 + wid] = ss; }
    __syncthreads();
    s  = sh[0] + sh[1] + sh[2] + sh[3];
    ss = sh[4] + sh[5] + sh[6] + sh[7];
    float mean = s * (1.0f / CND);
    float var  = ss * (1.0f / CND) - mean * mean;
    float rinv = rsqrtf(var + EPSF);
    int d = threadIdx.x * 4;
    float4 wv = *(const float4*)(w + d);
    float4 bv = *(const float4*)(b + d);
    uint2 u;
    u.x = pack_h2((v.x - mean) * rinv * wv.x + bv.x, (v.y - mean) * rinv * wv.y + bv.y);
    u.y = pack_h2((v.z - mean) * rinv * wv.z + bv.z, (v.w - mean) * rinv * wv.w + bv.w);
    ((uint2*)(out + (size_t)row * CND))[threadIdx.x] = u;
}

// ---------------- LN(h)*(1+scale)+shift -> half, width 1024 ----------------
__global__ void __launch_bounds__(256) ln_mod1024h(
    const float* __restrict__ x, const float* __restrict__ mod,
    int scale_off, int shift_off, __half* __restrict__ out)
{
    int row = blockIdx.x;
    float4 v = ((const float4*)(x + (size_t)row * CD))[threadIdx.x];
    float s  = v.x + v.y + v.z + v.w;
    float ss = v.x*v.x + v.y*v.y + v.z*v.z + v.w*v.w;
    s = warp_sum(s); ss = warp_sum(ss);
    __shared__ float sh[16];
    int wid = threadIdx.x >> 5, lid = threadIdx.x & 31;
    if (lid == 0) { sh[wid] = s; sh[8 + wid] = ss; }
    __syncthreads();
    s = 0.f; ss = 0.f;
#pragma unroll
    for (int i = 0; i < 8; i++) { s += sh[i]; ss += sh[8 + i]; }
    float mean = s * (1.0f / CD);
    float var  = ss * (1.0f / CD) - mean * mean;
    float rinv = rsqrtf(var + EPSF);
    int d = threadIdx.x * 4;
    const float* mrow = mod + (size_t)row * MODW;
    float4 sc = *(const float4*)(mrow + scale_off + d);
    float4 sf = *(const float4*)(mrow + shift_off + d);
    uint2 u;
    u.x = pack_h2(((v.x - mean) * rinv) * (1.0f + sc.x) + sf.x,
                  ((v.y - mean) * rinv) * (1.0f + sc.y) + sf.y);
    u.y = pack_h2(((v.z - mean) * rinv) * (1.0f + sc.z) + sf.z,
                  ((v.w - mean) * rinv) * (1.0f + sc.w) + sf.w);
    ((uint2*)(out + (size_t)row * CD))[threadIdx.x] = u;
}

// ---------------- fp16 NT GEMM, 128x128 tile (large-grid shapes) ----------------
#define ST_STRIDE (128 * 20)
#define GEMM_SMEM_128 (3 * 2 * ST_STRIDE * 4)   // 60 KB
template<int EPI>
__global__ void __launch_bounds__(256, 2) gemm_h(
    const __half* __restrict__ A, const __half* __restrict__ W,
    const float* __restrict__ bias, void* __restrict__ Cv,
    int M, int N, int K,
    const float* __restrict__ res, const float* __restrict__ gate, int gate_off)
{
    extern __shared__ uint32_t dynh[];
    uint32_t* As = dynh;
    uint32_t* Ws = dynh + 3 * ST_STRIDE;

    int bm = blockIdx.y * 128;
    int bn = blockIdx.x * 128;
    int tid  = threadIdx.x;
    int warp = tid >> 5, lane = tid & 31;
    int g = lane >> 2, t = lane & 3;
    int wm = (warp & 1) * 64;
    int wn = (warp >> 1) * 32;

    int lmA_row = lane & 15;
    int lmA_koff = (lane >> 4) * 4;
    int lmB_row = ((lane >> 4) * 8) + (lane & 7);
    int lmB_koff = ((lane >> 3) & 1) * 4;

    float acc[4][4][4];
#pragma unroll
    for (int i = 0; i < 4; i++)
#pragma unroll
        for (int j = 0; j < 4; j++)
#pragma unroll
            for (int q = 0; q < 4; q++) acc[i][j][q] = 0.f;

    int lrow0 = tid >> 2, lseg0 = tid & 3;
    int lrow1 = (tid + 256) >> 2, lseg1 = tid & 3;

    int nIter = K >> 5;

#pragma unroll
    for (int s = 0; s < 2; s++) {
        uint32_t* Ab = As + s * ST_STRIDE;
        uint32_t* Wb = Ws + s * ST_STRIDE;
        int k0 = s << 5;
        uint32_t da0 = (uint32_t)__cvta_generic_to_shared(&Ab[lrow0 * 20 + lseg0 * 4]);
        CP_ASYNC16(da0, A + (size_t)(bm + lrow0) * K + k0 + lseg0 * 8);
        uint32_t da1 = (uint32_t)__cvta_generic_to_shared(&Ab[lrow1 * 20 + lseg1 * 4]);
        CP_ASYNC16(da1, A + (size_t)(bm + lrow1) * K + k0 + lseg1 * 8);
        uint32_t dw0 = (uint32_t)__cvta_generic_to_shared(&Wb[lrow0 * 20 + lseg0 * 4]);
        CP_ASYNC16(dw0, W + (size_t)(bn + lrow0) * K + k0 + lseg0 * 8);
        uint32_t dw1 = (uint32_t)__cvta_generic_to_shared(&Wb[lrow1 * 20 + lseg1 * 4]);
        CP_ASYNC16(dw1, W + (size_t)(bn + lrow1) * K + k0 + lseg1 * 8);
        CP_COMMIT();
    }

    int buf = 0;
    for (int it = 0; it < nIter; ++it) {
        if (it + 1 < nIter) { CP_WAIT(1); } else { CP_WAIT(0); }
        __syncthreads();

        if (it + 2 < nIter) {
            int bnext = buf + 2; if (bnext >= 3) bnext -= 3;
            uint32_t* Ab = As + bnext * ST_STRIDE;
            uint32_t* Wb = Ws + bnext * ST_STRIDE;
            int k0 = (it + 2) << 5;
            uint32_t da0 = (uint32_t)__cvta_generic_to_shared(&Ab[lrow0 * 20 + lseg0 * 4]);
            CP_ASYNC16(da0, A + (size_t)(bm + lrow0) * K + k0 + lseg0 * 8);
            uint32_t da1 = (uint32_t)__cvta_generic_to_shared(&Ab[lrow1 * 20 + lseg1 * 4]);
            CP_ASYNC16(da1, A + (size_t)(bm + lrow1) * K + k0 + lseg1 * 8);
            uint32_t dw0 = (uint32_t)__cvta_generic_to_shared(&Wb[lrow0 * 20 + lseg0 * 4]);
            CP_ASYNC16(dw0, W + (size_t)(bn + lrow0) * K + k0 + lseg0 * 8);
            uint32_t dw1 = (uint32_t)__cvta_generic_to_shared(&Wb[lrow1 * 20 + lseg1 * 4]);
            CP_ASYNC16(dw1, W + (size_t)(bn + lrow1) * K + k0 + lseg1 * 8);
            CP_COMMIT();
        }

        const uint32_t* Ab = As + buf * ST_STRIDE;
        const uint32_t* Wb = Ws + buf * ST_STRIDE;
#pragma unroll
        for (int ks = 0; ks < 2; ks++) {
            int kp = ks * 8;
            uint32_t af[4][4];
#pragma unroll
            for (int mt = 0; mt < 4; mt++) {
                int r0 = wm + mt * 16;
                uint32_t addr = (uint32_t)__cvta_generic_to_shared(
                    &Ab[(size_t)(r0 + lmA_row) * 20 + kp + lmA_koff]);
                ldsm_x4(af[mt][0], af[mt][1], af[mt][2], af[mt][3], addr);
            }
            uint32_t bf[4][2];
#pragma unroll
            for (int np = 0; np < 2; np++) {
                int c0 = wn + np * 16;
                uint32_t addr = (uint32_t)__cvta_generic_to_shared(
                    &Wb[(size_t)(c0 + lmB_row) * 20 + kp + lmB_koff]);
                ldsm_x4(bf[2*np][0], bf[2*np][1], bf[2*np+1][0], bf[2*np+1][1], addr);
            }
#pragma unroll
            for (int mt = 0; mt < 4; mt++)
#pragma unroll
                for (int nt = 0; nt < 4; nt++)
                    mma_fp16(acc[mt][nt], af[mt], bf[nt]);
        }
        buf++; if (buf >= 3) buf = 0;
    }

#pragma unroll
    for (int mt = 0; mt < 4; mt++) {
#pragma unroll
        for (int half = 0; half < 2; half++) {
            int row = bm + wm + mt * 16 + g + half * 8;
            const float* rr = (EPI == 2) ? res + (size_t)row * N : nullptr;
            const float* gr = (EPI == 2) ? gate + (size_t)row * MODW + gate_off : nullptr;
#pragma unroll
            for (int nt = 0; nt < 4; nt++) {
                int col = bn + wn + nt * 8 + 2 * t;
                float v0 = acc[mt][nt][half * 2 + 0] + bias[col];
                float v1 = acc[mt][nt][half * 2 + 1] + bias[col + 1];
                if (EPI == 1) {
                    v0 = v0 / (1.0f + expf(-v0));
                    v1 = v1 / (1.0f + expf(-v1));
                }
                if (EPI == 1 || EPI == 3) {
                    __half* cr = (__half*)Cv + (size_t)row * N;
                    *(uint32_t*)(cr + col) = pack_h2(v0, v1);
                } else {
                    if (EPI == 2) {
                        v0 = rr[col]     + v0 * gr[col];
                        v1 = rr[col + 1] + v1 * gr[col + 1];
                    }
                    float* cr = (float*)Cv + (size_t)row * N;
                    float2 o2; o2.x = v0; o2.y = v1;
                    *(float2*)(cr + col) = o2;
                }
            }
        }
    }
}

// ---------------- fp16 NT GEMM, 64x128 tile (small-grid shapes) ----------------
#define ST_A (64 * 20)
#define ST_W (128 * 20)
#define GEMM_SMEM_64 (3 * (ST_A + ST_W) * 4)   // 46 KB
template<int EPI>
__global__ void __launch_bounds__(256, 3) gemm_h64(
    const __half* __restrict__ A, const __half* __restrict__ W,
    const float* __restrict__ bias, void* __restrict__ Cv,
    int M, int N, int K,
    const float* __restrict__ res, const float* __restrict__ gate, int gate_off)
{
    extern __shared__ uint32_t dynh[];
    uint32_t* As = dynh;
    uint32_t* Ws = dynh + 3 * ST_A;

    int bm = blockIdx.y * 64;
    int bn = blockIdx.x * 128;
    int tid  = threadIdx.x;
    int warp = tid >> 5, lane = tid & 31;
    int g = lane >> 2, t = lane & 3;
    int wm = (warp & 1) * 32;
    int wn = (warp >> 1) * 32;

    int lmA_row = lane & 15;
    int lmA_koff = (lane >> 4) * 4;
    int lmB_row = ((lane >> 4) * 8) + (lane & 7);
    int lmB_koff = ((lane >> 3) & 1) * 4;

    float acc[2][4][4];
#pragma unroll
    for (int i = 0; i < 2; i++)
#pragma unroll
        for (int j = 0; j < 4; j++)
#pragma unroll
            for (int q = 0; q < 4; q++) acc[i][j][q] = 0.f;

    int arow = tid >> 2,  aseg = tid & 3;
    int wrow0 = tid >> 2, wseg = tid & 3;
    int wrow1 = (tid + 256) >> 2;

    int nIter = K >> 5;

#pragma unroll
    for (int s = 0; s < 2; s++) {
        uint32_t* Ab = As + s * ST_A;
        uint32_t* Wb = Ws + s * ST_W;
        int k0 = s << 5;
        uint32_t da = (uint32_t)__cvta_generic_to_shared(&Ab[arow * 20 + aseg * 4]);
        CP_ASYNC16(da, A + (size_t)(bm + arow) * K + k0 + aseg * 8);
        uint32_t dw0 = (uint32_t)__cvta_generic_to_shared(&Wb[wrow0 * 20 + wseg * 4]);
        CP_ASYNC16(dw0, W + (size_t)(bn + wrow0) * K + k0 + wseg * 8);
        uint32_t dw1 = (uint32_t)__cvta_generic_to_shared(&Wb[wrow1 * 20 + wseg * 4]);
        CP_ASYNC16(dw1, W + (size_t)(bn + wrow1) * K + k0 + wseg * 8);
        CP_COMMIT();
    }

    int buf = 0;
    for (int it = 0; it < nIter; ++it) {
        if (it + 1 < nIter) { CP_WAIT(1); } else { CP_WAIT(0); }
        __syncthreads();

        if (it + 2 < nIter) {
            int bnext = buf + 2; if (bnext >= 3) bnext -= 3;
            uint32_t* Ab = As + bnext * ST_A;
            uint32_t* Wb = Ws + bnext * ST_W;
            int k0 = (it + 2) << 5;
            uint32_t da = (uint32_t)__cvta_generic_to_shared(&Ab[arow * 20 + aseg * 4]);
            CP_ASYNC16(da, A + (size_t)(bm + arow) * K + k0 + aseg * 8);
            uint32_t dw0 = (uint32_t)__cvta_generic_to_shared(&Wb[wrow0 * 20 + wseg * 4]);
            CP_ASYNC16(dw0, W + (size_t)(bn + wrow0) * K + k0 + wseg * 8);
            uint32_t dw1 = (uint32_t)__cvta_generic_to_shared(&Wb[wrow1 * 20 + wseg * 4]);
            CP_ASYNC16(dw1, W + (size_t)(bn + wrow1) * K + k0 + wseg * 8);
            CP_COMMIT();
        }

        const uint32_t* Ab = As + buf * ST_A;
        const uint32_t* Wb = Ws + buf * ST_W;
#pragma unroll
        for (int ks = 0; ks < 2; ks++) {
            int kp = ks * 8;
            uint32_t af[2][4];
#pragma unroll
            for (int mt = 0; mt < 2; mt++) {
                int r0 = wm + mt * 16;
                uint32_t addr = (uint32_t)__cvta_generic_to_shared(
                    &Ab[(size_t)(r0 + lmA_row) * 20 + kp + lmA_koff]);
                ldsm_x4(af[mt][0], af[mt][1], af[mt][2], af[mt][3], addr);
            }
            uint32_t bf[4][2];
#pragma unroll
            for (int np = 0; np < 2; np++) {
                int c0 = wn + np * 16;
                uint32_t addr = (uint32_t)__cvta_generic_to_shared(
                    &Wb[(size_t)(c0 + lmB_row) * 20 + kp + lmB_koff]);
                ldsm_x4(bf[2*np][0], bf[2*np][1], bf[2*np+1][0], bf[2*np+1][1], addr);
            }
#pragma unroll
            for (int mt = 0; mt < 2; mt++)
#pragma unroll
                for (int nt = 0; nt < 4; nt++)
                    mma_fp16(acc[mt][nt], af[mt], bf[nt]);
        }
        buf++; if (buf >= 3) buf = 0;
    }

#pragma unroll
    for (int mt = 0; mt < 2; mt++) {
#pragma unroll
        for (int half = 0; half < 2; half++) {
            int row = bm + wm + mt * 16 + g + half * 8;
            const float* rr = (EPI == 2) ? res + (size_t)row * N : nullptr;
            const float* gr = (EPI == 2) ? gate + (size_t)row * MODW + gate_off : nullptr;
#pragma unroll
            for (int nt = 0; nt < 4; nt++) {
                int col = bn + wn + nt * 8 + 2 * t;
                float v0 = acc[mt][nt][half * 2 + 0] + bias[col];
                float v1 = acc[mt][nt][half * 2 + 1] + bias[col + 1];
                if (EPI == 1) {
                    v0 = v0 / (1.0f + expf(-v0));
                    v1 = v1 / (1.0f + expf(-v1));
                }
                if (EPI == 1 || EPI == 3) {
                    __half* cr = (__half*)Cv + (size_t)row * N;
                    *(uint32_t*)(cr + col) = pack_h2(v0, v1);
                } else {
                    if (EPI == 2) {
                        v0 = rr[col]     + v0 * gr[col];
                        v1 = rr[col + 1] + v1 * gr[col + 1];
                    }
                    float* cr = (float*)Cv + (size_t)row * N;
                    float2 o2; o2.x = v0; o2.y = v1;
                    *(float2*)(cr + col) = o2;
                }
            }
        }
    }
}

// ---------------- edge bias (frozen since round 9) ----------------
__global__ void __launch_bounds__(128) edge_bias_mma(
    const float* __restrict__ p, const float* __restrict__ lnw, const float* __restrict__ lnb,
    const float* __restrict__ ew, const float* __restrict__ eb, __half* __restrict__ bias)
{
    __shared__ float rows[128][68];
    __shared__ float W2T[16][68];
    __shared__ float meanv[128], rinvv[128], c1s[16], c2s[16];
    int tid = threadIdx.x;
    size_t base = (size_t)blockIdx.x * 128;

#pragma unroll
    for (int r = 0; r < 16; r++) {
        int id  = tid + r * 128;
        int row = id >> 4;
        int c4  = (id & 15) * 4;
        *(float4*)&rows[row][c4] = *(const float4*)(p + (base + row) * 64 + c4);
    }
    for (int i = tid; i < 1024; i += 128) {
        int h = i >> 6, k = i & 63;
        W2T[h][k] = ew[i] * lnw[k];
    }
    if (tid < 16) {
        float a = 0.f, b2 = 0.f;
        for (int k = 0; k < 64; k++) {
            float e = ew[tid * 64 + k];
            a  += lnw[k] * e;
            b2 += lnb[k] * e;
        }
        c1s[tid] = a;
        c2s[tid] = b2 + eb[tid];
    }
    __syncthreads();

    {
        float s = 0.f, ss = 0.f;
#pragma unroll
        for (int q = 0; q < 16; q++) {
            float4 x = *(const float4*)&rows[tid][q * 4];
            s  += x.x + x.y + x.z + x.w;
            ss += x.x*x.x + x.y*x.y + x.z*x.z + x.w*x.w;
        }
        float mean = s * (1.0f / 64.0f);
        float var  = ss * (1.0f / 64.0f) - mean * mean;
        meanv[tid] = mean;
        rinvv[tid] = rsqrtf(var + EPSF);
    }
    __syncthreads();

    int warp = tid >> 5, lane = tid & 31;
    int g = lane >> 2, t = lane & 3;
    float acc[2][2][4];
#pragma unroll
    for (int i = 0; i < 2; i++)
#pragma unroll
        for (int j = 0; j < 2; j++)
#pragma unroll
            for (int q = 0; q < 4; q++) acc[i][j][q] = 0.f;

#pragma unroll
    for (int ks = 0; ks < 8; ks++) {
        int kk = ks * 8;
        uint32_t af[2][4];
#pragma unroll
        for (int mt = 0; mt < 2; mt++) {
            int r0 = warp * 32 + mt * 16 + g;
            af[mt][0] = __float_as_uint(rows[r0][kk + t]);
            af[mt][1] = __float_as_uint(rows[r0 + 8][kk + t]);
            af[mt][2] = __float_as_uint(rows[r0][kk + t + 4]);
            af[mt][3] = __float_as_uint(rows[r0 + 8][kk + t + 4]);
        }
        uint32_t bf[2][2];
#pragma unroll
        for (int nt = 0; nt < 2; nt++) {
            int c0 = nt * 8 + g;
            bf[nt][0] = __float_as_uint(W2T[c0][kk + t]);
            bf[nt][1] = __float_as_uint(W2T[c0][kk + t + 4]);
        }
#pragma unroll
        for (int mt = 0; mt < 2; mt++)
#pragma unroll
            for (int nt = 0; nt < 2; nt++)
                mma_tf32(acc[mt][nt], af[mt], bf[nt]);
    }

    int b  = (int)(base >> 18);
    int ij = (int)(base & 262143);
    int i  = ij >> 9;
    int j0 = ij & 511;
    __half* bb = bias + (((size_t)b * 16) * 512 + i) * 512 + j0;
#pragma unroll
    for (int mt = 0; mt < 2; mt++) {
#pragma unroll
        for (int half = 0; half < 2; half++) {
            int rl = warp * 32 + mt * 16 + g + half * 8;
            float m  = meanv[rl];
            float rv = rinvv[rl];
#pragma unroll
            for (int nt = 0; nt < 2; nt++) {
#pragma unroll
                for (int c = 0; c < 2; c++) {
                    int h = nt * 8 + 2 * t + c;
                    bb[(size_t)h * 512 * 512 + rl] =
                        __float2half(rv * (acc[mt][nt][half * 2 + c] - m * c1s[h]) + c2s[h]);
                }
            }
        }
    }
}

// ---------------- flash v2: all-fp16 MMA, register-resident P ----------------
__global__ void __launch_bounds__(256) flash_h(
    const __half* __restrict__ bias, const __half* __restrict__ qkvh, __half* __restrict__ o)
{
    __shared__ uint32_t Qh[128 * 36];
    __shared__ uint32_t Kh[64 * 36];
    __shared__ uint32_t Vt[64 * 36];

    int bh = blockIdx.y; int b = bh >> 4, h = bh & 15;
    int i0 = blockIdx.x * 128;
    int tid  = threadIdx.x;
    int warp = tid >> 5, lane = tid & 31;
    int g = lane >> 2, t = lane & 3;
    int r0 = warp * 16 + g;

    const __half* qb = qkvh + (size_t)(b * CL) * (3 * CD) + h * CDH;
    const __half* kb = qb + CD;
    const __half* vb = qb + 2 * CD;
    const __half* bbase = bias + ((size_t)bh * CL + i0) * CL;

#pragma unroll
    for (int r = 0; r < 4; r++) {
        int id  = tid + r * 256;
        int row = id >> 3, seg = id & 7;
        uint32_t dst = (uint32_t)__cvta_generic_to_shared(&Qh[row * 36 + seg * 4]);
        CP_ASYNC16(dst, qb + (size_t)(i0 + row) * (3 * CD) + seg * 8);
    }
    CP_COMMIT();

    float Oa[8][4];
#pragma unroll
    for (int nt = 0; nt < 8; nt++)
#pragma unroll
        for (int q = 0; q < 4; q++) Oa[nt][q] = 0.f;
    float m0 = -1e30f, m1 = -1e30f, l0 = 0.f, l1 = 0.f;

    for (int j0 = 0; j0 < CL; j0 += 64) {
#pragma unroll
        for (int r = 0; r < 2; r++) {
            int id  = tid + r * 256;
            int row = id >> 3, seg = id & 7;
            uint32_t dst = (uint32_t)__cvta_generic_to_shared(&Kh[row * 36 + seg * 4]);
            CP_ASYNC16(dst, kb + (size_t)(j0 + row) * (3 * CD) + seg * 8);
        }
        CP_COMMIT();
#pragma unroll
        for (int r = 0; r < 2; r++) {
            int jw = (tid >> 4) + r * 16;
            int dg = tid & 15;
            const __half* va = vb + (size_t)(j0 + 2 * jw) * (3 * CD) + dg * 4;
            uint2 ua = *(const uint2*)va;
            uint2 ub = *(const uint2*)(va + 3 * CD);
            Vt[(dg * 4 + 0) * 36 + jw] = (ua.x & 0xFFFFu)  | (ub.x << 16);
            Vt[(dg * 4 + 1) * 36 + jw] = (ua.x >> 16)      | (ub.x & 0xFFFF0000u);
            Vt[(dg * 4 + 2) * 36 + jw] = (ua.y & 0xFFFFu)  | (ub.y << 16);
            Vt[(dg * 4 + 3) * 36 + jw] = (ua.y >> 16)      | (ub.y & 0xFFFF0000u);
        }
        CP_WAIT(0);
        __syncthreads();

        float sa[8][4];
#pragma unroll
        for (int nt = 0; nt < 8; nt++)
#pragma unroll
            for (int q = 0; q < 4; q++) sa[nt][q] = 0.f;
#pragma unroll
        for (int ks = 0; ks < 4; ks++) {
            int kp = ks * 8;
            uint32_t af[4];
            af[0] = Qh[r0 * 36 + kp + t];
            af[1] = Qh[(r0 + 8) * 36 + kp + t];
            af[2] = Qh[r0 * 36 + kp + t + 4];
            af[3] = Qh[(r0 + 8) * 36 + kp + t + 4];
#pragma unroll
            for (int nt = 0; nt < 8; nt++) {
                int c0 = nt * 8 + g;
                uint32_t bf[2];
                bf[0] = Kh[c0 * 36 + kp + t];
                bf[1] = Kh[c0 * 36 + kp + t + 4];
                mma_fp16(sa[nt], af, bf);
            }
        }

        float mt0 = -1e30f, mt1 = -1e30f;
#pragma unroll
        for (int nt = 0; nt < 8; nt++) {
            int col = j0 + nt * 8 + 2 * t;
            float2 b0 = __half22float2(*(const __half2*)(bbase + (size_t)r0 * CL + col));
            float2 b1 = __half22float2(*(const __half2*)(bbase + (size_t)(r0 + 8) * CL + col));
            sa[nt][0] = fmaf(sa[nt][0], 0.125f, b0.x);
            sa[nt][1] = fmaf(sa[nt][1], 0.125f, b0.y);
            sa[nt][2] = fmaf(sa[nt][2], 0.125f, b1.x);
            sa[nt][3] = fmaf(sa[nt][3], 0.125f, b1.y);
            mt0 = fmaxf(mt0, fmaxf(sa[nt][0], sa[nt][1]));
            mt1 = fmaxf(mt1, fmaxf(sa[nt][2], sa[nt][3]));
        }
#pragma unroll
        for (int x = 1; x <= 2; x <<= 1) {
            mt0 = fmaxf(mt0, __shfl_xor_sync(0xffffffffu, mt0, x));
            mt1 = fmaxf(mt1, __shfl_xor_sync(0xffffffffu, mt1, x));
        }
        float mn0 = fmaxf(m0, mt0), mn1 = fmaxf(m1, mt1);
        float sc0 = expf(m0 - mn0), sc1 = expf(m1 - mn1);
        m0 = mn0; m1 = mn1;

        float ps0 = 0.f, ps1 = 0.f;
#pragma unroll
        for (int nt = 0; nt < 8; nt++) {
            sa[nt][0] = expf(sa[nt][0] - m0);
            sa[nt][1] = expf(sa[nt][1] - m0);
            sa[nt][2] = expf(sa[nt][2] - m1);
            sa[nt][3] = expf(sa[nt][3] - m1);
            ps0 += sa[nt][0] + sa[nt][1];
            ps1 += sa[nt][2] + sa[nt][3];
        }
#pragma unroll
        for (int x = 1; x <= 2; x <<= 1) {
            ps0 += __shfl_xor_sync(0xffffffffu, ps0, x);
            ps1 += __shfl_xor_sync(0xffffffffu, ps1, x);
        }
        l0 = l0 * sc0 + ps0;
        l1 = l1 * sc1 + ps1;
#pragma unroll
        for (int nt = 0; nt < 8; nt++) {
            Oa[nt][0] *= sc0; Oa[nt][1] *= sc0;
            Oa[nt][2] *= sc1; Oa[nt][3] *= sc1;
        }

#pragma unroll
        for (int ks = 0; ks < 4; ks++) {
            uint32_t af[4];
            af[0] = pack_h2(sa[2*ks][0],     sa[2*ks][1]);
            af[1] = pack_h2(sa[2*ks][2],     sa[2*ks][3]);
            af[2] = pack_h2(sa[2*ks + 1][0], sa[2*ks + 1][1]);
            af[3] = pack_h2(sa[2*ks + 1][2], sa[2*ks + 1][3]);
#pragma unroll
            for (int nt = 0; nt < 8; nt++) {
                int c0 = nt * 8 + g;
                uint32_t bf[2];
                bf[0] = Vt[c0 * 36 + ks * 8 + t];
                bf[1] = Vt[c0 * 36 + ks * 8 + t + 4];
                mma_fp16(Oa[nt], af, bf);
            }
        }
        __syncthreads();
    }

    float il0 = 1.0f / l0, il1 = 1.0f / l1;
    __half* o0 = o + (size_t)(b * CL + i0 + r0) * CD + h * CDH;
    __half* o1 = o + (size_t)(b * CL + i0 + r0 + 8) * CD + h * CDH;
#pragma unroll
    for (int nt = 0; nt < 8; nt++) {
        int d = nt * 8 + 2 * t;
        *(uint32_t*)(o0 + d) = pack_h2(Oa[nt][0] * il0, Oa[nt][1] * il0);
        *(uint32_t*)(o1 + d) = pack_h2(Oa[nt][2] * il1, Oa[nt][3] * il1);
    }
}

// ---------------- launch ----------------
extern "C" void kernel_launch(void* const* d_in, const int* in_sizes, int n_in,
                              void* d_out, int out_size)
{
    const float* h_in  = (const float*)d_in[0];
    const float* s_in  = (const float*)d_in[1];
    const float* p_in  = (const float*)d_in[2];
    const float* aln_w = (const float*)d_in[3];
    const float* aln_b = (const float*)d_in[4];
    const float* aw1   = (const float*)d_in[5];
    const float* ab1   = (const float*)d_in[6];
    const float* aw2   = (const float*)d_in[7];
    const float* ab2   = (const float*)d_in[8];
    const float* eln_w = (const float*)d_in[9];
    const float* eln_b = (const float*)d_in[10];
    const float* ew    = (const float*)d_in[11];
    const float* eb    = (const float*)d_in[12];
    const float* in_w  = (const float*)d_in[13];
    const float* in_b  = (const float*)d_in[14];
    const float* out_w = (const float*)d_in[15];
    const float* out_b = (const float*)d_in[16];
    const float* mw1   = (const float*)d_in[17];
    const float* mb1   = (const float*)d_in[18];
    const float* mw2   = (const float*)d_in[19];
    const float* mb2   = (const float*)d_in[20];
    float* out = (float*)d_out;

    float *mod, *h2;
    __half *sln_h, *t1_h, *x_h, *qkv_h, *o_h, *t2_h, *biasb, *wh;
    cudaGetSymbolAddress((void**)&sln_h, g_sln_h);
    cudaGetSymbolAddress((void**)&t1_h,  g_t1_h);
    cudaGetSymbolAddress((void**)&mod,   g_mod);
    cudaGetSymbolAddress((void**)&biasb, g_bias);
    cudaGetSymbolAddress((void**)&x_h,   g_x_h);
    cudaGetSymbolAddress((void**)&qkv_h, g_qkv_h);
    cudaGetSymbolAddress((void**)&o_h,   g_o_h);
    cudaGetSymbolAddress((void**)&h2,    g_h2);
    cudaGetSymbolAddress((void**)&t2_h,  g_t2_h);
    cudaGetSymbolAddress((void**)&wh,    g_wh);

    cudaFuncSetAttribute(gemm_h<0>,   cudaFuncAttributeMaxDynamicSharedMemorySize, GEMM_SMEM_128);
    cudaFuncSetAttribute(gemm_h<1>,   cudaFuncAttributeMaxDynamicSharedMemorySize, GEMM_SMEM_128);
    cudaFuncSetAttribute(gemm_h<3>,   cudaFuncAttributeMaxDynamicSharedMemorySize, GEMM_SMEM_128);
    cudaFuncSetAttribute(gemm_h64<1>, cudaFuncAttributeMaxDynamicSharedMemorySize, GEMM_SMEM_64);
    cudaFuncSetAttribute(gemm_h64<2>, cudaFuncAttributeMaxDynamicSharedMemorySize, GEMM_SMEM_64);

    // ---- fork edge_bias onto the per-thread stream (harmless; kept) ----
    cudaEvent_t ev_fork, ev_join;
    cudaEventCreateWithFlags(&ev_fork, cudaEventDisableTiming);
    cudaEventCreateWithFlags(&ev_join, cudaEventDisableTiming);
    cudaEventRecord(ev_fork, 0);
    cudaStreamWaitEvent(cudaStreamPerThread, ev_fork, 0);
    edge_bias_mma<<<(CB * CL * CL) / 128, 128, 0, cudaStreamPerThread>>>(
        p_in, eln_w, eln_b, ew, eb, biasb);
    cudaEventRecord(ev_join, cudaStreamPerThread);

    // ---- main chain ----
    cvt_all<<<1024, 256>>>((const float4*)aw1, (const float4*)aw2, (const float4*)in_w,
                           (const float4*)out_w, (const float4*)mw1, (const float4*)mw2,
                           (uint2*)wh);

    // adaLN modulation chain
    ln_affine512h<<<NTOK, 128>>>(s_in, aln_w, aln_b, sln_h);
    gemm_h64<1><<<dim3(CND / 128, NTOK / 64), 256, GEMM_SMEM_64>>>(sln_h, wh + OFF_AW1, ab1,
        t1_h, NTOK, CND, CND, nullptr, nullptr, 0);
    gemm_h<0><<<dim3(MODW / 128, NTOK / 128), 256, GEMM_SMEM_128>>>(t1_h, wh + OFF_AW2, ab2,
        mod, NTOK, MODW, CND, nullptr, nullptr, 0);

    // attention branch
    ln_mod1024h<<<NTOK, 256>>>(h_in, mod, /*scale*/CD, /*shift*/0, x_h);
    gemm_h<3><<<dim3(3 * CD / 128, NTOK / 128), 256, GEMM_SMEM_128>>>(x_h, wh + OFF_INW, in_b,
        qkv_h, NTOK, 3 * CD, CD, nullptr, nullptr, 0);

    // join: flash needs the edge bias
    cudaStreamWaitEvent(0, ev_join, 0);
    flash_h<<<dim3(CL / 128, CB * CH), 256>>>(biasb, qkv_h, o_h);
    gemm_h64<2><<<dim3(CD / 128, NTOK / 64), 256, GEMM_SMEM_64>>>(o_h, wh + OFF_OUTW, out_b,
        h2, NTOK, CD, CD, h_in, mod, 2 * CD);

    // gated MLP branch
    ln_mod1024h<<<NTOK, 256>>>(h2, mod, /*scale*/4 * CD, /*shift*/3 * CD, x_h);
    gemm_h<1><<<dim3(CMLP / 128, NTOK / 128), 256, GEMM_SMEM_128>>>(x_h, wh + OFF_MW1, mb1,
        t2_h, NTOK, CMLP, CD, nullptr, nullptr, 0);
    gemm_h64<2><<<dim3(CD / 128, NTOK / 64), 256, GEMM_SMEM_64>>>(t2_h, wh + OFF_MW2, mb2,
        out, NTOK, CD, CMLP, h2, mod, 5 * CD);
    // events intentionally not destroyed (capture-legal; no device memory)
}

// round 17
// speedup vs baseline: 1.1066x; 1.0697x over previous
#include <cuda_runtime.h>
#include <cuda_fp16.h>
#include <math.h>
#include <stdint.h>

// Problem constants
#define CB   4
#define CL   512
#define CD   1024
#define CND  512
#define CED  64
#define CH   16
#define CMLP 2048
#define CDH  64
#define NTOK (CB*CL)        // 2048
#define MODW (6*CD)         // 6144
#define EPSF 1e-5f

// ---------------- scratch ----------------
__device__ __half g_sln_h[NTOK*CND];
__device__ __half g_t1_h[NTOK*CND];
__device__ float  g_mod[NTOK*MODW];
__device__ __half g_bias[(size_t)CB*CH*CL*CL];
__device__ __half g_x_h[NTOK*CD];
__device__ __half g_qkv_h[NTOK*3*CD];
__device__ __half g_o_h[NTOK*CD];
__device__ float  g_h2[NTOK*CD];
__device__ __half g_t2_h[NTOK*CMLP];
// fp16 weights
#define OFF_AW1  0
#define OFF_AW2  (OFF_AW1 + 512*512)
#define OFF_INW  (OFF_AW2 + 6144*512)
#define OFF_OUTW (OFF_INW + 3072*1024)
#define OFF_MW1  (OFF_OUTW + 1024*1024)
#define OFF_MW2  (OFF_MW1 + 2048*1024)
#define WH_TOTAL (OFF_MW2 + 1024*2048)
__device__ __half g_wh[WH_TOTAL];

// ---------------- utils ----------------
__device__ __forceinline__ float warp_sum(float v) {
#pragma unroll
    for (int o = 16; o > 0; o >>= 1) v += __shfl_xor_sync(0xffffffffu, v, o);
    return v;
}
__device__ __forceinline__ void mma_tf32(float c[4], const uint32_t a[4], const uint32_t b[2]) {
    asm volatile(
        "mma.sync.aligned.m16n8k8.row.col.f32.tf32.tf32.f32 "
        "{%0,%1,%2,%3}, {%4,%5,%6,%7}, {%8,%9}, {%0,%1,%2,%3};"
        : "+f"(c[0]), "+f"(c[1]), "+f"(c[2]), "+f"(c[3])
        : "r"(a[0]), "r"(a[1]), "r"(a[2]), "r"(a[3]), "r"(b[0]), "r"(b[1]));
}
__device__ __forceinline__ void mma_fp16(float c[4], const uint32_t a[4], const uint32_t b[2]) {
    asm volatile(
        "mma.sync.aligned.m16n8k16.row.col.f32.f16.f16.f32 "
        "{%0,%1,%2,%3}, {%4,%5,%6,%7}, {%8,%9}, {%0,%1,%2,%3};"
        : "+f"(c[0]), "+f"(c[1]), "+f"(c[2]), "+f"(c[3])
        : "r"(a[0]), "r"(a[1]), "r"(a[2]), "r"(a[3]), "r"(b[0]), "r"(b[1]));
}
__device__ __forceinline__ uint32_t pack_h2(float lo, float hi) {
    __half2 h = __floats2half2_rn(lo, hi);
    return *(uint32_t*)&h;
}
__device__ __forceinline__ void ldsm_x4(uint32_t& d0, uint32_t& d1, uint32_t& d2, uint32_t& d3,
                                        uint32_t addr) {
    asm volatile("ldmatrix.sync.aligned.m8n8.x4.shared.b16 {%0,%1,%2,%3}, [%4];"
        : "=r"(d0), "=r"(d1), "=r"(d2), "=r"(d3) : "r"(addr));
}
#define CP_ASYNC16(dst_u32, src_ptr) \
    asm volatile("cp.async.cg.shared.global [%0], [%1], 16;" :: "r"(dst_u32), "l"(src_ptr))
#define CP_COMMIT() asm volatile("cp.async.commit_group;")
#define CP_WAIT(n)  asm volatile("cp.async.wait_group %0;" :: "n"(n))

// ---------------- all weights fp32 -> fp16, one kernel ----------------
__global__ void __launch_bounds__(256) cvt_all(
    const float4* __restrict__ s0, const float4* __restrict__ s1,
    const float4* __restrict__ s2, const float4* __restrict__ s3,
    const float4* __restrict__ s4, const float4* __restrict__ s5,
    uint2* __restrict__ dst)
{
    const int n0 = 512*512/4, n1 = 6144*512/4, n2 = 3072*1024/4,
              n3 = 1024*1024/4, n4 = 2048*1024/4, n5 = 1024*2048/4;
    int total = n0 + n1 + n2 + n3 + n4 + n5;
    for (int i = blockIdx.x * 256 + threadIdx.x; i < total; i += gridDim.x * 256) {
        int j = i; const float4* s;
        if (j < n0) s = s0;
        else { j -= n0; if (j < n1) s = s1;
        else { j -= n1; if (j < n2) s = s2;
        else { j -= n2; if (j < n3) s = s3;
        else { j -= n3; if (j < n4) s = s4;
        else { j -= n4; s = s5; }}}}}
        float4 v = s[j];
        uint2 u; u.x = pack_h2(v.x, v.y); u.y = pack_h2(v.z, v.w);
        dst[i] = u;
    }
}

// ---------------- LN(s)*w+b -> half, width 512 ----------------
__global__ void __launch_bounds__(128) ln_affine512h(
    const float* __restrict__ x, const float* __restrict__ w,
    const float* __restrict__ b, __half* __restrict__ out)
{
    int row = blockIdx.x;
    const float4* xr = (const float4*)(x + (size_t)row * CND);
    float4 v = xr[threadIdx.x];
    float s  = v.x + v.y + v.z + v.w;
    float ss = v.x*v.x + v.y*v.y + v.z*v.z + v.w*v.w;
    s = warp_sum(s); ss = warp_sum(ss);
    __shared__ float sh[8];
    int wid = threadIdx.x >> 5, lid = threadIdx.x & 31;
    if (lid == 0) { sh[wid] = s; sh[4 + wid] = ss; }
    __syncthreads();
    s  = sh[0] + sh[1] + sh[2] + sh[3];
    ss = sh[4] + sh[5] + sh[6] + sh[7];
    float mean = s * (1.0f / CND);
    float var  = ss * (1.0f / CND) - mean * mean;
    float rinv = rsqrtf(var + EPSF);
    int d = threadIdx.x * 4;
    float4 wv = *(const float4*)(w + d);
    float4 bv = *(const float4*)(b + d);
    uint2 u;
    u.x = pack_h2((v.x - mean) * rinv * wv.x + bv.x, (v.y - mean) * rinv * wv.y + bv.y);
    u.y = pack_h2((v.z - mean) * rinv * wv.z + bv.z, (v.w - mean) * rinv * wv.w + bv.w);
    ((uint2*)(out + (size_t)row * CND))[threadIdx.x] = u;
}

// ---------------- LN(h)*(1+scale)+shift -> half, width 1024 ----------------
__global__ void __launch_bounds__(256) ln_mod1024h(
    const float* __restrict__ x, const float* __restrict__ mod,
    int scale_off, int shift_off, __half* __restrict__ out)
{
    int row = blockIdx.x;
    float4 v = ((const float4*)(x + (size_t)row * CD))[threadIdx.x];
    float s  = v.x + v.y + v.z + v.w;
    float ss = v.x*v.x + v.y*v.y + v.z*v.z + v.w*v.w;
    s = warp_sum(s); ss = warp_sum(ss);
    __shared__ float sh[16];
    int wid = threadIdx.x >> 5, lid = threadIdx.x & 31;
    if (lid == 0) { sh[wid] = s; sh[8 + wid] = ss; }
    __syncthreads();
    s = 0.f; ss = 0.f;
#pragma unroll
    for (int i = 0; i < 8; i++) { s += sh[i]; ss += sh[8 + i]; }
    float mean = s * (1.0f / CD);
    float var  = ss * (1.0f / CD) - mean * mean;
    float rinv = rsqrtf(var + EPSF);
    int d = threadIdx.x * 4;
    const float* mrow = mod + (size_t)row * MODW;
    float4 sc = *(const float4*)(mrow + scale_off + d);
    float4 sf = *(const float4*)(mrow + shift_off + d);
    uint2 u;
    u.x = pack_h2(((v.x - mean) * rinv) * (1.0f + sc.x) + sf.x,
                  ((v.y - mean) * rinv) * (1.0f + sc.y) + sf.y);
    u.y = pack_h2(((v.z - mean) * rinv) * (1.0f + sc.z) + sf.z,
                  ((v.w - mean) * rinv) * (1.0f + sc.w) + sf.w);
    ((uint2*)(out + (size_t)row * CD))[threadIdx.x] = u;
}

// ---------------- fp16 NT GEMM, 128x128 tile (large-grid shapes) ----------------
#define ST_STRIDE (128 * 20)
#define GEMM_SMEM_128 (3 * 2 * ST_STRIDE * 4)   // 60 KB
template<int EPI>
__global__ void __launch_bounds__(256, 2) gemm_h(
    const __half* __restrict__ A, const __half* __restrict__ W,
    const float* __restrict__ bias, void* __restrict__ Cv,
    int M, int N, int K,
    const float* __restrict__ res, const float* __restrict__ gate, int gate_off)
{
    extern __shared__ uint32_t dynh[];
    uint32_t* As = dynh;
    uint32_t* Ws = dynh + 3 * ST_STRIDE;

    int bm = blockIdx.y * 128;
    int bn = blockIdx.x * 128;
    int tid  = threadIdx.x;
    int warp = tid >> 5, lane = tid & 31;
    int g = lane >> 2, t = lane & 3;
    int wm = (warp & 1) * 64;
    int wn = (warp >> 1) * 32;

    int lmA_row = lane & 15;
    int lmA_koff = (lane >> 4) * 4;
    int lmB_row = ((lane >> 4) * 8) + (lane & 7);
    int lmB_koff = ((lane >> 3) & 1) * 4;

    float acc[4][4][4];
#pragma unroll
    for (int i = 0; i < 4; i++)
#pragma unroll
        for (int j = 0; j < 4; j++)
#pragma unroll
            for (int q = 0; q < 4; q++) acc[i][j][q] = 0.f;

    int lrow0 = tid >> 2, lseg0 = tid & 3;
    int lrow1 = (tid + 256) >> 2, lseg1 = tid & 3;

    int nIter = K >> 5;

#pragma unroll
    for (int s = 0; s < 2; s++) {
        uint32_t* Ab = As + s * ST_STRIDE;
        uint32_t* Wb = Ws + s * ST_STRIDE;
        int k0 = s << 5;
        uint32_t da0 = (uint32_t)__cvta_generic_to_shared(&Ab[lrow0 * 20 + lseg0 * 4]);
        CP_ASYNC16(da0, A + (size_t)(bm + lrow0) * K + k0 + lseg0 * 8);
        uint32_t da1 = (uint32_t)__cvta_generic_to_shared(&Ab[lrow1 * 20 + lseg1 * 4]);
        CP_ASYNC16(da1, A + (size_t)(bm + lrow1) * K + k0 + lseg1 * 8);
        uint32_t dw0 = (uint32_t)__cvta_generic_to_shared(&Wb[lrow0 * 20 + lseg0 * 4]);
        CP_ASYNC16(dw0, W + (size_t)(bn + lrow0) * K + k0 + lseg0 * 8);
        uint32_t dw1 = (uint32_t)__cvta_generic_to_shared(&Wb[lrow1 * 20 + lseg1 * 4]);
        CP_ASYNC16(dw1, W + (size_t)(bn + lrow1) * K + k0 + lseg1 * 8);
        CP_COMMIT();
    }

    int buf = 0;
    for (int it = 0; it < nIter; ++it) {
        if (it + 1 < nIter) { CP_WAIT(1); } else { CP_WAIT(0); }
        __syncthreads();

        if (it + 2 < nIter) {
            int bnext = buf + 2; if (bnext >= 3) bnext -= 3;
            uint32_t* Ab = As + bnext * ST_STRIDE;
            uint32_t* Wb = Ws + bnext * ST_STRIDE;
            int k0 = (it + 2) << 5;
            uint32_t da0 = (uint32_t)__cvta_generic_to_shared(&Ab[lrow0 * 20 + lseg0 * 4]);
            CP_ASYNC16(da0, A + (size_t)(bm + lrow0) * K + k0 + lseg0 * 8);
            uint32_t da1 = (uint32_t)__cvta_generic_to_shared(&Ab[lrow1 * 20 + lseg1 * 4]);
            CP_ASYNC16(da1, A + (size_t)(bm + lrow1) * K + k0 + lseg1 * 8);
            uint32_t dw0 = (uint32_t)__cvta_generic_to_shared(&Wb[lrow0 * 20 + lseg0 * 4]);
            CP_ASYNC16(dw0, W + (size_t)(bn + lrow0) * K + k0 + lseg0 * 8);
            uint32_t dw1 = (uint32_t)__cvta_generic_to_shared(&Wb[lrow1 * 20 + lseg1 * 4]);
            CP_ASYNC16(dw1, W + (size_t)(bn + lrow1) * K + k0 + lseg1 * 8);
            CP_COMMIT();
        }

        const uint32_t* Ab = As + buf * ST_STRIDE;
        const uint32_t* Wb = Ws + buf * ST_STRIDE;
#pragma unroll
        for (int ks = 0; ks < 2; ks++) {
            int kp = ks * 8;
            uint32_t af[4][4];
#pragma unroll
            for (int mt = 0; mt < 4; mt++) {
                int r0 = wm + mt * 16;
                uint32_t addr = (uint32_t)__cvta_generic_to_shared(
                    &Ab[(size_t)(r0 + lmA_row) * 20 + kp + lmA_koff]);
                ldsm_x4(af[mt][0], af[mt][1], af[mt][2], af[mt][3], addr);
            }
            uint32_t bf[4][2];
#pragma unroll
            for (int np = 0; np < 2; np++) {
                int c0 = wn + np * 16;
                uint32_t addr = (uint32_t)__cvta_generic_to_shared(
                    &Wb[(size_t)(c0 + lmB_row) * 20 + kp + lmB_koff]);
                ldsm_x4(bf[2*np][0], bf[2*np][1], bf[2*np+1][0], bf[2*np+1][1], addr);
            }
#pragma unroll
            for (int mt = 0; mt < 4; mt++)
#pragma unroll
                for (int nt = 0; nt < 4; nt++)
                    mma_fp16(acc[mt][nt], af[mt], bf[nt]);
        }
        buf++; if (buf >= 3) buf = 0;
    }

#pragma unroll
    for (int mt = 0; mt < 4; mt++) {
#pragma unroll
        for (int half = 0; half < 2; half++) {
            int row = bm + wm + mt * 16 + g + half * 8;
            const float* rr = (EPI == 2) ? res + (size_t)row * N : nullptr;
            const float* gr = (EPI == 2) ? gate + (size_t)row * MODW + gate_off : nullptr;
#pragma unroll
            for (int nt = 0; nt < 4; nt++) {
                int col = bn + wn + nt * 8 + 2 * t;
                float v0 = acc[mt][nt][half * 2 + 0] + bias[col];
                float v1 = acc[mt][nt][half * 2 + 1] + bias[col + 1];
                if (EPI == 1) {
                    v0 = v0 / (1.0f + expf(-v0));
                    v1 = v1 / (1.0f + expf(-v1));
                }
                if (EPI == 1 || EPI == 3) {
                    __half* cr = (__half*)Cv + (size_t)row * N;
                    *(uint32_t*)(cr + col) = pack_h2(v0, v1);
                } else {
                    if (EPI == 2) {
                        v0 = rr[col]     + v0 * gr[col];
                        v1 = rr[col + 1] + v1 * gr[col + 1];
                    }
                    float* cr = (float*)Cv + (size_t)row * N;
                    float2 o2; o2.x = v0; o2.y = v1;
                    *(float2*)(cr + col) = o2;
                }
            }
        }
    }
}

// ---------------- fp16 NT GEMM, 64x128 tile (small-grid shapes) ----------------
#define ST_A (64 * 20)
#define ST_W (128 * 20)
#define GEMM_SMEM_64 (3 * (ST_A + ST_W) * 4)   // 46 KB
template<int EPI>
__global__ void __launch_bounds__(256, 3) gemm_h64(
    const __half* __restrict__ A, const __half* __restrict__ W,
    const float* __restrict__ bias, void* __restrict__ Cv,
    int M, int N, int K,
    const float* __restrict__ res, const float* __restrict__ gate, int gate_off)
{
    extern __shared__ uint32_t dynh[];
    uint32_t* As = dynh;
    uint32_t* Ws = dynh + 3 * ST_A;

    int bm = blockIdx.y * 64;
    int bn = blockIdx.x * 128;
    int tid  = threadIdx.x;
    int warp = tid >> 5, lane = tid & 31;
    int g = lane >> 2, t = lane & 3;
    int wm = (warp & 1) * 32;
    int wn = (warp >> 1) * 32;

    int lmA_row = lane & 15;
    int lmA_koff = (lane >> 4) * 4;
    int lmB_row = ((lane >> 4) * 8) + (lane & 7);
    int lmB_koff = ((lane >> 3) & 1) * 4;

    float acc[2][4][4];
#pragma unroll
    for (int i = 0; i < 2; i++)
#pragma unroll
        for (int j = 0; j < 4; j++)
#pragma unroll
            for (int q = 0; q < 4; q++) acc[i][j][q] = 0.f;

    int arow = tid >> 2,  aseg = tid & 3;
    int wrow0 = tid >> 2, wseg = tid & 3;
    int wrow1 = (tid + 256) >> 2;

    int nIter = K >> 5;

#pragma unroll
    for (int s = 0; s < 2; s++) {
        uint32_t* Ab = As + s * ST_A;
        uint32_t* Wb = Ws + s * ST_W;
        int k0 = s << 5;
        uint32_t da = (uint32_t)__cvta_generic_to_shared(&Ab[arow * 20 + aseg * 4]);
        CP_ASYNC16(da, A + (size_t)(bm + arow) * K + k0 + aseg * 8);
        uint32_t dw0 = (uint32_t)__cvta_generic_to_shared(&Wb[wrow0 * 20 + wseg * 4]);
        CP_ASYNC16(dw0, W + (size_t)(bn + wrow0) * K + k0 + wseg * 8);
        uint32_t dw1 = (uint32_t)__cvta_generic_to_shared(&Wb[wrow1 * 20 + wseg * 4]);
        CP_ASYNC16(dw1, W + (size_t)(bn + wrow1) * K + k0 + wseg * 8);
        CP_COMMIT();
    }

    int buf = 0;
    for (int it = 0; it < nIter; ++it) {
        if (it + 1 < nIter) { CP_WAIT(1); } else { CP_WAIT(0); }
        __syncthreads();

        if (it + 2 < nIter) {
            int bnext = buf + 2; if (bnext >= 3) bnext -= 3;
            uint32_t* Ab = As + bnext * ST_A;
            uint32_t* Wb = Ws + bnext * ST_W;
            int k0 = (it + 2) << 5;
            uint32_t da = (uint32_t)__cvta_generic_to_shared(&Ab[arow * 20 + aseg * 4]);
            CP_ASYNC16(da, A + (size_t)(bm + arow) * K + k0 + aseg * 8);
            uint32_t dw0 = (uint32_t)__cvta_generic_to_shared(&Wb[wrow0 * 20 + wseg * 4]);
            CP_ASYNC16(dw0, W + (size_t)(bn + wrow0) * K + k0 + wseg * 8);
            uint32_t dw1 = (uint32_t)__cvta_generic_to_shared(&Wb[wrow1 * 20 + wseg * 4]);
            CP_ASYNC16(dw1, W + (size_t)(bn + wrow1) * K + k0 + wseg * 8);
            CP_COMMIT();
        }

        const uint32_t* Ab = As + buf * ST_A;
        const uint32_t* Wb = Ws + buf * ST_W;
#pragma unroll
        for (int ks = 0; ks < 2; ks++) {
            int kp = ks * 8;
            uint32_t af[2][4];
#pragma unroll
            for (int mt = 0; mt < 2; mt++) {
                int r0 = wm + mt * 16;
                uint32_t addr = (uint32_t)__cvta_generic_to_shared(
                    &Ab[(size_t)(r0 + lmA_row) * 20 + kp + lmA_koff]);
                ldsm_x4(af[mt][0], af[mt][1], af[mt][2], af[mt][3], addr);
            }
            uint32_t bf[4][2];
#pragma unroll
            for (int np = 0; np < 2; np++) {
                int c0 = wn + np * 16;
                uint32_t addr = (uint32_t)__cvta_generic_to_shared(
                    &Wb[(size_t)(c0 + lmB_row) * 20 + kp + lmB_koff]);
                ldsm_x4(bf[2*np][0], bf[2*np][1], bf[2*np+1][0], bf[2*np+1][1], addr);
            }
#pragma unroll
            for (int mt = 0; mt < 2; mt++)
#pragma unroll
                for (int nt = 0; nt < 4; nt++)
                    mma_fp16(acc[mt][nt], af[mt], bf[nt]);
        }
        buf++; if (buf >= 3) buf = 0;
    }

#pragma unroll
    for (int mt = 0; mt < 2; mt++) {
#pragma unroll
        for (int half = 0; half < 2; half++) {
            int row = bm + wm + mt * 16 + g + half * 8;
            const float* rr = (EPI == 2) ? res + (size_t)row * N : nullptr;
            const float* gr = (EPI == 2) ? gate + (size_t)row * MODW + gate_off : nullptr;
#pragma unroll
            for (int nt = 0; nt < 4; nt++) {
                int col = bn + wn + nt * 8 + 2 * t;
                float v0 = acc[mt][nt][half * 2 + 0] + bias[col];
                float v1 = acc[mt][nt][half * 2 + 1] + bias[col + 1];
                if (EPI == 1) {
                    v0 = v0 / (1.0f + expf(-v0));
                    v1 = v1 / (1.0f + expf(-v1));
                }
                if (EPI == 1 || EPI == 3) {
                    __half* cr = (__half*)Cv + (size_t)row * N;
                    *(uint32_t*)(cr + col) = pack_h2(v0, v1);
                } else {
                    if (EPI == 2) {
                        v0 = rr[col]     + v0 * gr[col];
                        v1 = rr[col + 1] + v1 * gr[col + 1];
                    }
                    float* cr = (float*)Cv + (size_t)row * N;
                    float2 o2; o2.x = v0; o2.y = v1;
                    *(float2*)(cr + col) = o2;
                }
            }
        }
    }
}

// ---------------- edge bias v5: 2-tile cp.async pipeline per CTA ----------------
// grid 4096, block 128. smem: rows[2][128][68] | W2T[16][68] | meanv | rinvv | c1s | c2s
#define EB_ROWS (128 * 68)
#define EB_SMEM ((2 * EB_ROWS + 16 * 68 + 128 + 128 + 16 + 16) * 4)
__global__ void __launch_bounds__(128) edge_bias_mma(
    const float* __restrict__ p, const float* __restrict__ lnw, const float* __restrict__ lnb,
    const float* __restrict__ ew, const float* __restrict__ eb, __half* __restrict__ bias)
{
    extern __shared__ float esm[];
    float* rowsbuf = esm;                      // [2][128][68]
    float* W2T   = esm + 2 * EB_ROWS;          // [16][68]
    float* meanv = W2T + 16 * 68;
    float* rinvv = meanv + 128;
    float* c1s   = rinvv + 128;
    float* c2s   = c1s + 16;

    int tid = threadIdx.x;
    size_t base = (size_t)blockIdx.x * 256;

    // issue both tiles' p loads up front (cp.async)
#pragma unroll
    for (int tt = 0; tt < 2; tt++) {
        float* rb = rowsbuf + tt * EB_ROWS;
        size_t tb = base + tt * 128;
#pragma unroll
        for (int r = 0; r < 16; r++) {
            int id  = tid + r * 128;
            int row = id >> 4;
            int c4  = (id & 15) * 4;
            uint32_t dst = (uint32_t)__cvta_generic_to_shared(&rb[row * 68 + c4]);
            CP_ASYNC16(dst, p + (tb + row) * 64 + c4);
        }
        CP_COMMIT();
    }

    // W2T / c1s / c2s in the shadow of the async loads
    for (int i = tid; i < 1024; i += 128) {
        int h = i >> 6, k = i & 63;
        W2T[h * 68 + k] = ew[i] * lnw[k];
    }
    if (tid < 16) {
        float a = 0.f, b2 = 0.f;
        for (int k = 0; k < 64; k++) {
            float e = ew[tid * 64 + k];
            a  += lnw[k] * e;
            b2 += lnb[k] * e;
        }
        c1s[tid] = a;
        c2s[tid] = b2 + eb[tid];
    }

    int warp = tid >> 5, lane = tid & 31;
    int g = lane >> 2, t = lane & 3;

#pragma unroll
    for (int tt = 0; tt < 2; tt++) {
        if (tt == 0) { CP_WAIT(1); } else { CP_WAIT(0); }
        __syncthreads();   // tile tt data visible; (tt=1) also orders tile0 meanv reads before rewrite

        const float* rows = rowsbuf + tt * EB_ROWS;

        // per-row stats (thread <-> row)
        {
            float s = 0.f, ss = 0.f;
#pragma unroll
            for (int q = 0; q < 16; q++) {
                float4 x = *(const float4*)&rows[tid * 68 + q * 4];
                s  += x.x + x.y + x.z + x.w;
                ss += x.x*x.x + x.y*x.y + x.z*x.z + x.w*x.w;
            }
            float mean = s * (1.0f / 64.0f);
            float var  = ss * (1.0f / 64.0f) - mean * mean;
            meanv[tid] = mean;
            rinvv[tid] = rsqrtf(var + EPSF);
        }
        __syncthreads();

        float acc[2][2][4];
#pragma unroll
        for (int i = 0; i < 2; i++)
#pragma unroll
            for (int j = 0; j < 2; j++)
#pragma unroll
                for (int q = 0; q < 4; q++) acc[i][j][q] = 0.f;

#pragma unroll
        for (int ks = 0; ks < 8; ks++) {
            int kk = ks * 8;
            uint32_t af[2][4];
#pragma unroll
            for (int mt = 0; mt < 2; mt++) {
                int r0 = warp * 32 + mt * 16 + g;
                af[mt][0] = __float_as_uint(rows[r0 * 68 + kk + t]);
                af[mt][1] = __float_as_uint(rows[(r0 + 8) * 68 + kk + t]);
                af[mt][2] = __float_as_uint(rows[r0 * 68 + kk + t + 4]);
                af[mt][3] = __float_as_uint(rows[(r0 + 8) * 68 + kk + t + 4]);
            }
            uint32_t bf[2][2];
#pragma unroll
            for (int nt = 0; nt < 2; nt++) {
                int c0 = nt * 8 + g;
                bf[nt][0] = __float_as_uint(W2T[c0 * 68 + kk + t]);
                bf[nt][1] = __float_as_uint(W2T[c0 * 68 + kk + t + 4]);
            }
#pragma unroll
            for (int mt = 0; mt < 2; mt++)
#pragma unroll
                for (int nt = 0; nt < 2; nt++)
                    mma_tf32(acc[mt][nt], af[mt], bf[nt]);
        }

        size_t tb = base + tt * 128;
        int b  = (int)(tb >> 18);
        int ij = (int)(tb & 262143);
        int i  = ij >> 9;
        int j0 = ij & 511;
        __half* bb = bias + (((size_t)b * 16) * 512 + i) * 512 + j0;
#pragma unroll
        for (int mt = 0; mt < 2; mt++) {
#pragma unroll
            for (int half = 0; half < 2; half++) {
                int rl = warp * 32 + mt * 16 + g + half * 8;
                float m  = meanv[rl];
                float rv = rinvv[rl];
#pragma unroll
                for (int nt = 0; nt < 2; nt++) {
#pragma unroll
                    for (int c = 0; c < 2; c++) {
                        int h = nt * 8 + 2 * t + c;
                        bb[(size_t)h * 512 * 512 + rl] =
                            __float2half(rv * (acc[mt][nt][half * 2 + c] - m * c1s[h]) + c2s[h]);
                    }
                }
            }
        }
    }
}

// ---------------- flash v2: all-fp16 MMA, register-resident P ----------------
__global__ void __launch_bounds__(256) flash_h(
    const __half* __restrict__ bias, const __half* __restrict__ qkvh, __half* __restrict__ o)
{
    __shared__ uint32_t Qh[128 * 36];
    __shared__ uint32_t Kh[64 * 36];
    __shared__ uint32_t Vt[64 * 36];

    int bh = blockIdx.y; int b = bh >> 4, h = bh & 15;
    int i0 = blockIdx.x * 128;
    int tid  = threadIdx.x;
    int warp = tid >> 5, lane = tid & 31;
    int g = lane >> 2, t = lane & 3;
    int r0 = warp * 16 + g;

    const __half* qb = qkvh + (size_t)(b * CL) * (3 * CD) + h * CDH;
    const __half* kb = qb + CD;
    const __half* vb = qb + 2 * CD;
    const __half* bbase = bias + ((size_t)bh * CL + i0) * CL;

#pragma unroll
    for (int r = 0; r < 4; r++) {
        int id  = tid + r * 256;
        int row = id >> 3, seg = id & 7;
        uint32_t dst = (uint32_t)__cvta_generic_to_shared(&Qh[row * 36 + seg * 4]);
        CP_ASYNC16(dst, qb + (size_t)(i0 + row) * (3 * CD) + seg * 8);
    }
    CP_COMMIT();

    float Oa[8][4];
#pragma unroll
    for (int nt = 0; nt < 8; nt++)
#pragma unroll
        for (int q = 0; q < 4; q++) Oa[nt][q] = 0.f;
    float m0 = -1e30f, m1 = -1e30f, l0 = 0.f, l1 = 0.f;

    for (int j0 = 0; j0 < CL; j0 += 64) {
#pragma unroll
        for (int r = 0; r < 2; r++) {
            int id  = tid + r * 256;
            int row = id >> 3, seg = id & 7;
            uint32_t dst = (uint32_t)__cvta_generic_to_shared(&Kh[row * 36 + seg * 4]);
            CP_ASYNC16(dst, kb + (size_t)(j0 + row) * (3 * CD) + seg * 8);
        }
        CP_COMMIT();
#pragma unroll
        for (int r = 0; r < 2; r++) {
            int jw = (tid >> 4) + r * 16;
            int dg = tid & 15;
            const __half* va = vb + (size_t)(j0 + 2 * jw) * (3 * CD) + dg * 4;
            uint2 ua = *(const uint2*)va;
            uint2 ub = *(const uint2*)(va + 3 * CD);
            Vt[(dg * 4 + 0) * 36 + jw] = (ua.x & 0xFFFFu)  | (ub.x << 16);
            Vt[(dg * 4 + 1) * 36 + jw] = (ua.x >> 16)      | (ub.x & 0xFFFF0000u);
            Vt[(dg * 4 + 2) * 36 + jw] = (ua.y & 0xFFFFu)  | (ub.y << 16);
            Vt[(dg * 4 + 3) * 36 + jw] = (ua.y >> 16)      | (ub.y & 0xFFFF0000u);
        }
        CP_WAIT(0);
        __syncthreads();

        float sa[8][4];
#pragma unroll
        for (int nt = 0; nt < 8; nt++)
#pragma unroll
            for (int q = 0; q < 4; q++) sa[nt][q] = 0.f;
#pragma unroll
        for (int ks = 0; ks < 4; ks++) {
            int kp = ks * 8;
            uint32_t af[4];
            af[0] = Qh[r0 * 36 + kp + t];
            af[1] = Qh[(r0 + 8) * 36 + kp + t];
            af[2] = Qh[r0 * 36 + kp + t + 4];
            af[3] = Qh[(r0 + 8) * 36 + kp + t + 4];
#pragma unroll
            for (int nt = 0; nt < 8; nt++) {
                int c0 = nt * 8 + g;
                uint32_t bf[2];
                bf[0] = Kh[c0 * 36 + kp + t];
                bf[1] = Kh[c0 * 36 + kp + t + 4];
                mma_fp16(sa[nt], af, bf);
            }
        }

        float mt0 = -1e30f, mt1 = -1e30f;
#pragma unroll
        for (int nt = 0; nt < 8; nt++) {
            int col = j0 + nt * 8 + 2 * t;
            float2 b0 = __half22float2(*(const __half2*)(bbase + (size_t)r0 * CL + col));
            float2 b1 = __half22float2(*(const __half2*)(bbase + (size_t)(r0 + 8) * CL + col));
            sa[nt][0] = fmaf(sa[nt][0], 0.125f, b0.x);
            sa[nt][1] = fmaf(sa[nt][1], 0.125f, b0.y);
            sa[nt][2] = fmaf(sa[nt][2], 0.125f, b1.x);
            sa[nt][3] = fmaf(sa[nt][3], 0.125f, b1.y);
            mt0 = fmaxf(mt0, fmaxf(sa[nt][0], sa[nt][1]));
            mt1 = fmaxf(mt1, fmaxf(sa[nt][2], sa[nt][3]));
        }
#pragma unroll
        for (int x = 1; x <= 2; x <<= 1) {
            mt0 = fmaxf(mt0, __shfl_xor_sync(0xffffffffu, mt0, x));
            mt1 = fmaxf(mt1, __shfl_xor_sync(0xffffffffu, mt1, x));
        }
        float mn0 = fmaxf(m0, mt0), mn1 = fmaxf(m1, mt1);
        float sc0 = expf(m0 - mn0), sc1 = expf(m1 - mn1);
        m0 = mn0; m1 = mn1;

        float ps0 = 0.f, ps1 = 0.f;
#pragma unroll
        for (int nt = 0; nt < 8; nt++) {
            sa[nt][0] = expf(sa[nt][0] - m0);
            sa[nt][1] = expf(sa[nt][1] - m0);
            sa[nt][2] = expf(sa[nt][2] - m1);
            sa[nt][3] = expf(sa[nt][3] - m1);
            ps0 += sa[nt][0] + sa[nt][1];
            ps1 += sa[nt][2] + sa[nt][3];
        }
#pragma unroll
        for (int x = 1; x <= 2; x <<= 1) {
            ps0 += __shfl_xor_sync(0xffffffffu, ps0, x);
            ps1 += __shfl_xor_sync(0xffffffffu, ps1, x);
        }
        l0 = l0 * sc0 + ps0;
        l1 = l1 * sc1 + ps1;
#pragma unroll
        for (int nt = 0; nt < 8; nt++) {
            Oa[nt][0] *= sc0; Oa[nt][1] *= sc0;
            Oa[nt][2] *= sc1; Oa[nt][3] *= sc1;
        }

#pragma unroll
        for (int ks = 0; ks < 4; ks++) {
            uint32_t af[4];
            af[0] = pack_h2(sa[2*ks][0],     sa[2*ks][1]);
            af[1] = pack_h2(sa[2*ks][2],     sa[2*ks][3]);
            af[2] = pack_h2(sa[2*ks + 1][0], sa[2*ks + 1][1]);
            af[3] = pack_h2(sa[2*ks + 1][2], sa[2*ks + 1][3]);
#pragma unroll
            for (int nt = 0; nt < 8; nt++) {
                int c0 = nt * 8 + g;
                uint32_t bf[2];
                bf[0] = Vt[c0 * 36 + ks * 8 + t];
                bf[1] = Vt[c0 * 36 + ks * 8 + t + 4];
                mma_fp16(Oa[nt], af, bf);
            }
        }
        __syncthreads();
    }

    float il0 = 1.0f / l0, il1 = 1.0f / l1;
    __half* o0 = o + (size_t)(b * CL + i0 + r0) * CD + h * CDH;
    __half* o1 = o + (size_t)(b * CL + i0 + r0 + 8) * CD + h * CDH;
#pragma unroll
    for (int nt = 0; nt < 8; nt++) {
        int d = nt * 8 + 2 * t;
        *(uint32_t*)(o0 + d) = pack_h2(Oa[nt][0] * il0, Oa[nt][1] * il0);
        *(uint32_t*)(o1 + d) = pack_h2(Oa[nt][2] * il1, Oa[nt][3] * il1);
    }
}

// ---------------- launch ----------------
extern "C" void kernel_launch(void* const* d_in, const int* in_sizes, int n_in,
                              void* d_out, int out_size)
{
    const float* h_in  = (const float*)d_in[0];
    const float* s_in  = (const float*)d_in[1];
    const float* p_in  = (const float*)d_in[2];
    const float* aln_w = (const float*)d_in[3];
    const float* aln_b = (const float*)d_in[4];
    const float* aw1   = (const float*)d_in[5];
    const float* ab1   = (const float*)d_in[6];
    const float* aw2   = (const float*)d_in[7];
    const float* ab2   = (const float*)d_in[8];
    const float* eln_w = (const float*)d_in[9];
    const float* eln_b = (const float*)d_in[10];
    const float* ew    = (const float*)d_in[11];
    const float* eb    = (const float*)d_in[12];
    const float* in_w  = (const float*)d_in[13];
    const float* in_b  = (const float*)d_in[14];
    const float* out_w = (const float*)d_in[15];
    const float* out_b = (const float*)d_in[16];
    const float* mw1   = (const float*)d_in[17];
    const float* mb1   = (const float*)d_in[18];
    const float* mw2   = (const float*)d_in[19];
    const float* mb2   = (const float*)d_in[20];
    float* out = (float*)d_out;

    float *mod, *h2;
    __half *sln_h, *t1_h, *x_h, *qkv_h, *o_h, *t2_h, *biasb, *wh;
    cudaGetSymbolAddress((void**)&sln_h, g_sln_h);
    cudaGetSymbolAddress((void**)&t1_h,  g_t1_h);
    cudaGetSymbolAddress((void**)&mod,   g_mod);
    cudaGetSymbolAddress((void**)&biasb, g_bias);
    cudaGetSymbolAddress((void**)&x_h,   g_x_h);
    cudaGetSymbolAddress((void**)&qkv_h, g_qkv_h);
    cudaGetSymbolAddress((void**)&o_h,   g_o_h);
    cudaGetSymbolAddress((void**)&h2,    g_h2);
    cudaGetSymbolAddress((void**)&t2_h,  g_t2_h);
    cudaGetSymbolAddress((void**)&wh,    g_wh);

    cudaFuncSetAttribute(gemm_h<0>,   cudaFuncAttributeMaxDynamicSharedMemorySize, GEMM_SMEM_128);
    cudaFuncSetAttribute(gemm_h<1>,   cudaFuncAttributeMaxDynamicSharedMemorySize, GEMM_SMEM_128);
    cudaFuncSetAttribute(gemm_h<3>,   cudaFuncAttributeMaxDynamicSharedMemorySize, GEMM_SMEM_128);
    cudaFuncSetAttribute(gemm_h64<1>, cudaFuncAttributeMaxDynamicSharedMemorySize, GEMM_SMEM_64);
    cudaFuncSetAttribute(gemm_h64<2>, cudaFuncAttributeMaxDynamicSharedMemorySize, GEMM_SMEM_64);
    cudaFuncSetAttribute(edge_bias_mma, cudaFuncAttributeMaxDynamicSharedMemorySize, EB_SMEM);

    // ---- fork edge_bias onto the per-thread stream (harmless; kept) ----
    cudaEvent_t ev_fork, ev_join;
    cudaEventCreateWithFlags(&ev_fork, cudaEventDisableTiming);
    cudaEventCreateWithFlags(&ev_join, cudaEventDisableTiming);
    cudaEventRecord(ev_fork, 0);
    cudaStreamWaitEvent(cudaStreamPerThread, ev_fork, 0);
    edge_bias_mma<<<(CB * CL * CL) / 256, 128, EB_SMEM, cudaStreamPerThread>>>(
        p_in, eln_w, eln_b, ew, eb, biasb);
    cudaEventRecord(ev_join, cudaStreamPerThread);

    // ---- main chain ----
    cvt_all<<<1024, 256>>>((const float4*)aw1, (const float4*)aw2, (const float4*)in_w,
                           (const float4*)out_w, (const float4*)mw1, (const float4*)mw2,
                           (uint2*)wh);

    // adaLN modulation chain
    ln_affine512h<<<NTOK, 128>>>(s_in, aln_w, aln_b, sln_h);
    gemm_h64<1><<<dim3(CND / 128, NTOK / 64), 256, GEMM_SMEM_64>>>(sln_h, wh + OFF_AW1, ab1,
        t1_h, NTOK, CND, CND, nullptr, nullptr, 0);
    gemm_h<0><<<dim3(MODW / 128, NTOK / 128), 256, GEMM_SMEM_128>>>(t1_h, wh + OFF_AW2, ab2,
        mod, NTOK, MODW, CND, nullptr, nullptr, 0);

    // attention branch
    ln_mod1024h<<<NTOK, 256>>>(h_in, mod, /*scale*/CD, /*shift*/0, x_h);
    gemm_h<3><<<dim3(3 * CD / 128, NTOK / 128), 256, GEMM_SMEM_128>>>(x_h, wh + OFF_INW, in_b,
        qkv_h, NTOK, 3 * CD, CD, nullptr, nullptr, 0);

    // join: flash needs the edge bias
    cudaStreamWaitEvent(0, ev_join, 0);
    flash_h<<<dim3(CL / 128, CB * CH), 256>>>(biasb, qkv_h, o_h);
    gemm_h64<2><<<dim3(CD / 128, NTOK / 64), 256, GEMM_SMEM_64>>>(o_h, wh + OFF_OUTW, out_b,
        h2, NTOK, CD, CD, h_in, mod, 2 * CD);

    // gated MLP branch
    ln_mod1024h<<<NTOK, 256>>>(h2, mod, /*scale*/4 * CD, /*shift*/3 * CD, x_h);
    gemm_h<1><<<dim3(CMLP / 128, NTOK / 128), 256, GEMM_SMEM_128>>>(x_h, wh + OFF_MW1, mb1,
        t2_h, NTOK, CMLP, CD, nullptr, nullptr, 0);
    gemm_h64<2><<<dim3(CD / 128, NTOK / 64), 256, GEMM_SMEM_64>>>(t2_h, wh + OFF_MW2, mb2,
        out, NTOK, CD, CMLP, h2, mod, 5 * CD);
    // events intentionally not destroyed (capture-legal; no device memory)
}